// round 9
// baseline (speedup 1.0000x reference)
#include <cuda_runtime.h>
#include <cuda_fp16.h>
#include <math.h>
#include <stdint.h>

#define NMAX 100000
#define EMAX 1700000
#define FULLM 0xffffffffu

// Scratch: per-node P (cols 0..63, includes b1) and Q (cols 64..127). 51.2 MB.
__device__ float g_PQ[(size_t)NMAX * 128];
__device__ int2 g_edges[EMAX];    // packed (src, dst), input order
__device__ int2 g_sorted[EMAX];   // grouped by dst
__device__ unsigned g_hist[NMAX];
__device__ unsigned g_cursor[NMAX];
__device__ int g_is64;

__device__ __forceinline__ uint32_t smem_u32(const void* p) {
    uint32_t a;
    asm("{ .reg .u64 t; cvta.to.shared.u64 t, %1; cvt.u32.u64 %0, t; }"
        : "=r"(a) : "l"(p));
    return a;
}

// m16n8k16 row.col f32 += f16*f16
__device__ __forceinline__ void mma16816(float* c, const uint32_t* a,
                                         const uint32_t* b) {
    asm volatile(
        "mma.sync.aligned.m16n8k16.row.col.f32.f16.f16.f32 "
        "{%0,%1,%2,%3}, {%4,%5,%6,%7}, {%8,%9}, {%0,%1,%2,%3};"
        : "+f"(c[0]), "+f"(c[1]), "+f"(c[2]), "+f"(c[3])
        : "r"(a[0]), "r"(a[1]), "r"(a[2]), "r"(a[3]), "r"(b[0]), "r"(b[1]));
}

__device__ __forceinline__ void ldmatrix_x4(uint32_t* r, uint32_t addr) {
    asm volatile(
        "ldmatrix.sync.aligned.m8n8.x4.shared.b16 {%0,%1,%2,%3}, [%4];"
        : "=r"(r[0]), "=r"(r[1]), "=r"(r[2]), "=r"(r[3]) : "r"(addr));
}

// ===========================================================================
// Detect int64 vs int32 edge_index (jax x64-disabled emits int32).
// ===========================================================================
__global__ void detect_kernel(const unsigned int* __restrict__ ei) {
    __shared__ int any;
    if (threadIdx.x == 0) any = 0;
    __syncthreads();
    if (ei[2 * threadIdx.x + 1] != 0u) any = 1;  // benign race
    __syncthreads();
    if (threadIdx.x == 0) g_is64 = (any == 0) ? 1 : 0;
}

__global__ void zero_hist_kernel(int N) {
    int i = blockIdx.x * blockDim.x + threadIdx.x;
    if (i < N) g_hist[i] = 0u;
}

// Fused: edge_index (either width) -> packed int2, + dst histogram.
__global__ void convhist_kernel(const void* __restrict__ eidx, int E) {
    int i = blockIdx.x * blockDim.x + threadIdx.x;
    if (i >= E) return;
    int s, d;
    if (g_is64) {
        const long long* e64 = (const long long*)eidx;
        s = (int)e64[i];
        d = (int)e64[E + i];
    } else {
        const int* e32 = (const int*)eidx;
        s = e32[i];
        d = e32[E + i];
    }
    g_edges[i] = make_int2(s, d);
    atomicAdd(&g_hist[d], 1u);
}

// Single-block exclusive scan over N counters -> g_cursor.
__global__ __launch_bounds__(1024) void scan_kernel(int N) {
    __shared__ unsigned wsum[32];
    __shared__ unsigned carry_s;
    int tid = threadIdx.x, lane = tid & 31, w = tid >> 5;
    if (tid == 0) carry_s = 0u;
    __syncthreads();
    for (int base = 0; base < N; base += 1024) {
        int i = base + tid;
        unsigned v = (i < N) ? g_hist[i] : 0u;
        unsigned x = v;
#pragma unroll
        for (int o = 1; o < 32; o <<= 1) {
            unsigned y = __shfl_up_sync(FULLM, x, o);
            if (lane >= o) x += y;
        }
        if (lane == 31) wsum[w] = x;
        __syncthreads();
        if (w == 0) {
            unsigned s = wsum[lane];
#pragma unroll
            for (int o = 1; o < 32; o <<= 1) {
                unsigned y = __shfl_up_sync(FULLM, s, o);
                if (lane >= o) s += y;
            }
            wsum[lane] = s;
        }
        __syncthreads();
        unsigned incl = x + (w > 0 ? wsum[w - 1] : 0u) + carry_s;
        if (i < N) g_cursor[i] = incl - v;
        __syncthreads();  // all carry_s reads done
        if (tid == 1023) carry_s = incl;
        __syncthreads();
    }
}

__global__ void scatter_kernel(int E) {
    int i = blockIdx.x * blockDim.x + threadIdx.x;
    if (i >= E) return;
    int2 sd = g_edges[i];
    unsigned pos = atomicAdd(&g_cursor[sd.y], 1u);
    g_sorted[pos] = sd;
}

// ===========================================================================
// Node kernel: PQ[n] = [ x@(W1a-W1b)+b1 | x@W1b ],  x = [feat(64) | xyz(3)]
// ===========================================================================
__global__ __launch_bounds__(256) void node_pq_kernel(
    const float* __restrict__ xyz, const float* __restrict__ feat,
    const float* __restrict__ W1, const float* __restrict__ b1, int N) {
    __shared__ float ws[67][128];
    __shared__ float xs[32][68];

    int tid = threadIdx.x;
    for (int i = tid; i < 67 * 128; i += 256) {
        int k = i >> 7, c = i & 127;
        float w1b = W1[(k + 67) * 64 + (c & 63)];
        ws[k][c] = (c < 64) ? (W1[k * 64 + c] - w1b) : w1b;
    }
    int n0 = blockIdx.x * 32;
    for (int i = tid; i < 32 * 67; i += 256) {
        int n = i / 67, k = i - n * 67;
        int gn = n0 + n;
        float v = 0.f;
        if (gn < N) v = (k < 64) ? feat[(size_t)gn * 64 + k]
                                 : xyz[(size_t)gn * 3 + (k - 64)];
        xs[n][k] = v;
    }
    __syncthreads();

    int cg = tid & 31, ng = tid >> 5;
    int c0 = cg * 4, nr = ng * 4;
    float acc[4][4];
#pragma unroll
    for (int i = 0; i < 4; i++)
#pragma unroll
        for (int j = 0; j < 4; j++)
            acc[i][j] = (c0 < 64) ? b1[c0 + j] : 0.f;

#pragma unroll 67
    for (int k = 0; k < 67; k++) {
        float4 w = *(const float4*)&ws[k][c0];
#pragma unroll
        for (int i = 0; i < 4; i++) {
            float xv = xs[nr + i][k];
            acc[i][0] = fmaf(xv, w.x, acc[i][0]);
            acc[i][1] = fmaf(xv, w.y, acc[i][1]);
            acc[i][2] = fmaf(xv, w.z, acc[i][2]);
            acc[i][3] = fmaf(xv, w.w, acc[i][3]);
        }
    }
#pragma unroll
    for (int i = 0; i < 4; i++) {
        int gn = n0 + nr + i;
        if (gn < N) {
            float4 v = make_float4(acc[i][0], acc[i][1], acc[i][2], acc[i][3]);
            *(float4*)&g_PQ[(size_t)gn * 128 + c0] = v;
        }
    }
}

// ===========================================================================
// Init output to -inf bits (vectorized); finalize -inf -> 0
// ===========================================================================
__global__ void init_kernel(uint4* __restrict__ out, int n4) {
    int i = blockIdx.x * blockDim.x + threadIdx.x;
    if (i < n4)
        out[i] = make_uint4(0xff800000u, 0xff800000u, 0xff800000u, 0xff800000u);
}

__global__ void finalize_kernel(uint4* __restrict__ out, int n4) {
    int i = blockIdx.x * blockDim.x + threadIdx.x;
    if (i >= n4) return;
    uint4 v = out[i];
    bool ch = false;
    if (v.x == 0xff800000u) { v.x = 0u; ch = true; }
    if (v.y == 0xff800000u) { v.y = 0u; ch = true; }
    if (v.z == 0xff800000u) { v.z = 0u; ch = true; }
    if (v.w == 0xff800000u) { v.w = 0u; ch = true; }
    if (ch) out[i] = v;
}

// ===========================================================================
// Float atomic max via int/uint ordering trick (no return -> RED).
// ===========================================================================
__device__ __forceinline__ void atomic_max_f(float* a, float v) {
    if (v >= 0.f)
        atomicMax((int*)a, __float_as_int(v));
    else
        atomicMin((unsigned int*)a, __float_as_uint(v));
}

// ===========================================================================
// Edge HMMA kernel, v6: dst-sorted edges + CONTIGUOUS warp chunks +
// register segmented reduction. 128 threads = 4 warps, 4 CTAs/SM.
// Contiguous chunks make a node's edges live in ONE warp: P[dst] gathers and
// g_sorted reads become cache-resident, and each node-run emits few REDs.
// Per warp-tile (32 sorted edges):
//   cooperative gather -> z = relu(P[dst]+Q[src]) -> fp16 hi/lo -> SMEM
//   Y = zh@W + zl@W  (mma.sync m16n8k16 f16, fp32 accum, b2 in C-init)
//   Epilogue: ballot-delimited dst-segments reduced in registers (masked max
//   + 3-step shfl.xor butterfly), ONE RED per (segment, col). No out[] reads.
// ===========================================================================
__global__ __launch_bounds__(128, 4) void edge_mma_kernel(
    const float* __restrict__ W2, const float* __restrict__ b2,
    float* __restrict__ out, int E) {
    __shared__ char zbuf[4][8192];  // per warp: zh 4KB + zl 4KB
    __shared__ char wtile[8192];    // W2^T fp16 (64 rows n x 128B k)

    const int tid = threadIdx.x;
    const int lane = tid & 31;
    const int wid = tid >> 5;

    // ---- build swizzled W2^T fp16 in SMEM (once per CTA) ----
    for (int i = tid; i < 64 * 64; i += 128) {
        int n = i >> 6, k = i & 63;
        float w = W2[k * 64 + n];
        uint32_t off = (uint32_t)n * 128 + (((uint32_t)(2 * k)) ^ ((uint32_t)(n & 7) << 4));
        *(__half*)(&wtile[off]) = __float2half_rn(w);
    }
    __syncthreads();

    const uint32_t zh_base = smem_u32(&zbuf[wid][0]);
    const uint32_t zl_base = zh_base + 4096;
    const uint32_t w_base = smem_u32(&wtile[0]);

    // B-frag ldmatrix lane addressing (covers ks pair per x4)
    const uint32_t brow = lane & 7;
    const uint32_t bswz = brow << 4;
    const uint32_t bpart = (((uint32_t)lane >> 3) & 1) * 16 + (((uint32_t)lane >> 4) & 1) * 32;
    const uint32_t boff0 = brow * 128 + (bpart ^ bswz);        // ks0,ks1
    const uint32_t boff1 = brow * 128 + ((bpart + 64) ^ bswz); // ks2,ks3

    // A-frag ldmatrix lane addressing
    const int am = lane >> 3, rowin = lane & 7;
    const uint32_t lswz = (uint32_t)rowin << 4;
    const uint32_t akb = (uint32_t)((am >> 1) << 4);
    const int arow_in = ((am & 1) << 3) + rowin;

    const int rsel = lane >> 2;
    const int colb = (lane & 3) * 2;

    // b2 pairs register-resident
    float2 b2v[8];
#pragma unroll
    for (int nt = 0; nt < 8; nt++)
        b2v[nt] = *(const float2*)(b2 + nt * 8 + colb);

    // cooperative-gather lane pieces
    const int sub = lane >> 4;               // which edge of the pair
    const int cq = lane & 15;                // column quad (4 floats)
    const uint32_t cbyte = (uint32_t)cq * 8; // byte offset in fp16 row

    const float NEG_INF = __int_as_float(0xff800000);

    // ---- contiguous chunk assignment ----
    const int T = (E + 31) >> 5;
    const int nwarp = gridDim.x * 4;
    const int gw = blockIdx.x * 4 + wid;
    const int chunk = (T + nwarp - 1) / nwarp;
    int t = gw * chunk;
    const int tend = (t + chunk < T) ? t + chunk : T;
    if (t >= tend) return;

    int e0 = t * 32 + lane;
    int2 sd = g_sorted[(e0 < E) ? e0 : 0];

    for (; t < tend; t++) {
        int e = t * 32 + lane;
        bool valid = (e < E);
        int mydst = valid ? sd.y : -1;

        // segment boundaries (dst-sorted: equal dst are contiguous)
        unsigned vmask = __ballot_sync(FULLM, valid);
        int prevd = __shfl_up_sync(FULLM, mydst, 1);
        bool flag = valid && (lane == 0 || mydst != prevd);
        unsigned segb = __ballot_sync(FULLM, flag);

        __syncwarp();  // prior tile's ldmatrix reads done before overwrite

        // ---- cooperative gather + relu + fp16 hi/lo split -> SMEM ----
#pragma unroll 4
        for (int g = 0; g < 16; g++) {
            int esel = 2 * g + sub;
            int d = __shfl_sync(FULLM, sd.y, esel);
            int s = __shfl_sync(FULLM, sd.x, esel);
            float4 p = *((const float4*)(g_PQ + (size_t)d * 128) + cq);
            float4 q = *((const float4*)(g_PQ + (size_t)s * 128 + 64) + cq);
            float z0 = fmaxf(p.x + q.x, 0.f), z1 = fmaxf(p.y + q.y, 0.f);
            float z2 = fmaxf(p.z + q.z, 0.f), z3 = fmaxf(p.w + q.w, 0.f);
            __half2 h01 = __floats2half2_rn(z0, z1);
            __half2 h23 = __floats2half2_rn(z2, z3);
            float2 f01 = __half22float2(h01);
            float2 f23 = __half22float2(h23);
            __half2 l01 = __floats2half2_rn(z0 - f01.x, z1 - f01.y);
            __half2 l23 = __floats2half2_rn(z2 - f23.x, z3 - f23.y);
            uint32_t row = (uint32_t)(2 * g + sub);
            uint32_t off = row * 128 + (cbyte ^ ((row & 7) << 4));
            asm volatile("st.shared.v2.b32 [%0], {%1,%2};"
                         :: "r"(zh_base + off),
                            "r"(*(uint32_t*)&h01), "r"(*(uint32_t*)&h23));
            asm volatile("st.shared.v2.b32 [%0], {%1,%2};"
                         :: "r"(zl_base + off),
                            "r"(*(uint32_t*)&l01), "r"(*(uint32_t*)&l23));
        }
        __syncwarp();

        // ---- prefetch next tile's edge record (sequential; hides latency) ----
        if (t + 1 < tend) {
            int en = (t + 1) * 32 + lane;
            sd = g_sorted[(en < E) ? en : 0];
        }

#pragma unroll
        for (int mt = 0; mt < 2; mt++) {
            // A fragments for this 16-row slice (zh + zl, 4 k-steps)
            uint32_t ah[4][4], al[4][4];
            uint32_t rowb = (uint32_t)(mt * 16 + arow_in) * 128;
#pragma unroll
            for (int ks = 0; ks < 4; ks++) {
                uint32_t off = rowb + (((uint32_t)ks * 32 + akb) ^ lswz);
                ldmatrix_x4(ah[ks], zh_base + off);
                ldmatrix_x4(al[ks], zl_base + off);
            }

            // dst of this lane's two fragment rows
            int d0 = __shfl_sync(FULLM, mydst, mt * 16 + rsel);
            int d1 = __shfl_sync(FULLM, mydst, mt * 16 + 8 + rsel);

            // segments overlapping this mt half
            unsigned mtseg;
            if (mt == 0) {
                mtseg = segb & 0xFFFFu;
            } else {
                mtseg = segb & 0xFFFF0000u;
                unsigned lo = segb & 0xFFFFu;
                bool l16v = (vmask >> 16) & 1u;
                bool l16s = (segb >> 16) & 1u;
                if (l16v && !l16s && lo)
                    mtseg |= (1u << (31 - __clz(lo)));  // straddling segment
            }

#pragma unroll
            for (int nt = 0; nt < 8; nt++) {
                uint32_t bw[4][2];
                uint32_t wb = (uint32_t)nt * 1024;
                ldmatrix_x4(&bw[0][0], w_base + wb + boff0);
                ldmatrix_x4(&bw[2][0], w_base + wb + boff1);

                float c[4] = {b2v[nt].x, b2v[nt].y, b2v[nt].x, b2v[nt].y};
#pragma unroll
                for (int ks = 0; ks < 4; ks++) mma16816(c, ah[ks], bw[ks]);
#pragma unroll
                for (int ks = 0; ks < 4; ks++) mma16816(c, al[ks], bw[ks]);

                // ---- register segmented max + one RED per (segment,col) ----
                unsigned b = mtseg;
                while (b) {
                    int sl = __ffs(b) - 1;
                    b &= b - 1;
                    int D = __shfl_sync(FULLM, mydst, sl);
                    float m0 = NEG_INF, m1 = NEG_INF;
                    if (d0 == D) { m0 = c[0]; m1 = c[1]; }
                    if (d1 == D) { m0 = fmaxf(m0, c[2]); m1 = fmaxf(m1, c[3]); }
#pragma unroll
                    for (int o = 4; o <= 16; o <<= 1) {
                        m0 = fmaxf(m0, __shfl_xor_sync(FULLM, m0, o));
                        m1 = fmaxf(m1, __shfl_xor_sync(FULLM, m1, o));
                    }
                    if (lane < 4 && __float_as_uint(m0) != 0xff800000u) {
                        float* o = out + (size_t)D * 64 + nt * 8 + lane * 2;
                        atomic_max_f(o, m0);
                        atomic_max_f(o + 1, m1);
                    }
                }
            }
        }
    }
}

// ===========================================================================
// Inputs: [0]=xyz (N*3 f32), [1]=feat (N*64 f32), [2]=edge_index (2*E int),
//         [3]=W1 (134*64 f32), [4]=b1 (64), [5]=W2 (64*64), [6]=b2 (64)
// ===========================================================================
extern "C" void kernel_launch(void* const* d_in, const int* in_sizes, int n_in,
                              void* d_out, int out_size) {
    const float* xyz  = (const float*)d_in[0];
    const float* feat = (const float*)d_in[1];
    const void*  eidx = d_in[2];
    const float* W1   = (const float*)d_in[3];
    const float* b1   = (const float*)d_in[4];
    const float* W2   = (const float*)d_in[5];
    const float* b2   = (const float*)d_in[6];
    float* out = (float*)d_out;

    int N = in_sizes[0] / 3;
    int E = in_sizes[2] / 2;
    int outn = N * 64;
    int n4 = outn / 4;

    detect_kernel<<<1, 1024>>>((const unsigned int*)eidx);
    zero_hist_kernel<<<(N + 255) / 256, 256>>>(N);
    convhist_kernel<<<(E + 255) / 256, 256>>>(eidx, E);
    scan_kernel<<<1, 1024>>>(N);
    scatter_kernel<<<(E + 255) / 256, 256>>>(E);
    node_pq_kernel<<<(N + 31) / 32, 256>>>(xyz, feat, W1, b1, N);
    init_kernel<<<(n4 + 255) / 256, 256>>>((uint4*)out, n4);

    int Twarp = (E + 31) >> 5;
    int grid = 4 * 148;  // persistent, 4 CTAs/SM
    if (grid > (Twarp + 3) / 4) grid = (Twarp + 3) / 4;
    edge_mma_kernel<<<grid, 128>>>(W2, b2, out, E);

    finalize_kernel<<<(n4 + 255) / 256, 256>>>((uint4*)out, n4);
}

// round 10
// speedup vs baseline: 1.1268x; 1.1268x over previous
#include <cuda_runtime.h>
#include <cuda_fp16.h>
#include <math.h>
#include <stdint.h>

#define NMAX 100000
#define EMAX 1700000
#define FULLM 0xffffffffu

// Scratch: per-node P (cols 0..63, includes b1) and Q (cols 64..127). 51.2 MB.
__device__ float g_PQ[(size_t)NMAX * 128];
__device__ int2 g_edges[EMAX];    // packed (src, dst), input order
__device__ int2 g_sorted[EMAX];   // grouped by dst
__device__ unsigned g_hist[NMAX];
__device__ unsigned g_cursor[NMAX];
__device__ unsigned g_blocksum[128];
__device__ int g_is64;

__device__ __forceinline__ uint32_t smem_u32(const void* p) {
    uint32_t a;
    asm("{ .reg .u64 t; cvta.to.shared.u64 t, %1; cvt.u32.u64 %0, t; }"
        : "=r"(a) : "l"(p));
    return a;
}

// m16n8k16 row.col f32 += f16*f16
__device__ __forceinline__ void mma16816(float* c, const uint32_t* a,
                                         const uint32_t* b) {
    asm volatile(
        "mma.sync.aligned.m16n8k16.row.col.f32.f16.f16.f32 "
        "{%0,%1,%2,%3}, {%4,%5,%6,%7}, {%8,%9}, {%0,%1,%2,%3};"
        : "+f"(c[0]), "+f"(c[1]), "+f"(c[2]), "+f"(c[3])
        : "r"(a[0]), "r"(a[1]), "r"(a[2]), "r"(a[3]), "r"(b[0]), "r"(b[1]));
}

__device__ __forceinline__ void ldmatrix_x4(uint32_t* r, uint32_t addr) {
    asm volatile(
        "ldmatrix.sync.aligned.m8n8.x4.shared.b16 {%0,%1,%2,%3}, [%4];"
        : "=r"(r[0]), "=r"(r[1]), "=r"(r[2]), "=r"(r[3]) : "r"(addr));
}

// ===========================================================================
// Detect int64 vs int32 edge_index (jax x64-disabled emits int32).
// ===========================================================================
__global__ void detect_kernel(const unsigned int* __restrict__ ei) {
    __shared__ int any;
    if (threadIdx.x == 0) any = 0;
    __syncthreads();
    if (ei[2 * threadIdx.x + 1] != 0u) any = 1;  // benign race
    __syncthreads();
    if (threadIdx.x == 0) g_is64 = (any == 0) ? 1 : 0;
}

__global__ void zero_hist_kernel(int N) {
    int i = blockIdx.x * blockDim.x + threadIdx.x;
    if (i < N) g_hist[i] = 0u;
}

// Fused: edge_index (either width) -> packed int2, + dst histogram.
__global__ void convhist_kernel(const void* __restrict__ eidx, int E) {
    int i = blockIdx.x * blockDim.x + threadIdx.x;
    if (i >= E) return;
    int s, d;
    if (g_is64) {
        const long long* e64 = (const long long*)eidx;
        s = (int)e64[i];
        d = (int)e64[E + i];
    } else {
        const int* e32 = (const int*)eidx;
        s = e32[i];
        d = e32[E + i];
    }
    g_edges[i] = make_int2(s, d);
    atomicAdd(&g_hist[d], 1u);
}

// ===========================================================================
// Multi-block exclusive scan of g_hist -> g_cursor (3 passes).
// ===========================================================================
__global__ __launch_bounds__(1024) void scan1_kernel(int N) {
    __shared__ unsigned wsum[32];
    int tid = threadIdx.x, lane = tid & 31, w = tid >> 5;
    int i = blockIdx.x * 1024 + tid;
    unsigned v = (i < N) ? g_hist[i] : 0u;
    unsigned x = v;
#pragma unroll
    for (int o = 1; o < 32; o <<= 1) {
        unsigned y = __shfl_up_sync(FULLM, x, o);
        if (lane >= o) x += y;
    }
    if (lane == 31) wsum[w] = x;
    __syncthreads();
    if (w == 0) {
        unsigned s = wsum[lane];
#pragma unroll
        for (int o = 1; o < 32; o <<= 1) {
            unsigned y = __shfl_up_sync(FULLM, s, o);
            if (lane >= o) s += y;
        }
        wsum[lane] = s;
    }
    __syncthreads();
    unsigned incl = x + (w > 0 ? wsum[w - 1] : 0u);
    if (i < N) g_cursor[i] = incl - v;  // exclusive within block
    if (tid == 1023) g_blocksum[blockIdx.x] = incl;
}

// Single small block: exclusive scan of <=128 block sums in place.
__global__ void scan2_kernel(int nb) {
    __shared__ unsigned ws[4];
    int tid = threadIdx.x, lane = tid & 31, w = tid >> 5;
    unsigned v = (tid < nb) ? g_blocksum[tid] : 0u;
    unsigned x = v;
#pragma unroll
    for (int o = 1; o < 32; o <<= 1) {
        unsigned y = __shfl_up_sync(FULLM, x, o);
        if (lane >= o) x += y;
    }
    if (lane == 31) ws[w] = x;
    __syncthreads();
    unsigned add = 0;
    for (int j = 0; j < w; j++) add += ws[j];
    if (tid < nb) g_blocksum[tid] = x + add - v;  // exclusive
}

__global__ void scan3_kernel(int N) {
    int i = blockIdx.x * blockDim.x + threadIdx.x;
    if (i < N) g_cursor[i] += g_blocksum[i >> 10];
}

__global__ void scatter_kernel(int E) {
    int i = blockIdx.x * blockDim.x + threadIdx.x;
    if (i >= E) return;
    int2 sd = g_edges[i];
    unsigned pos = atomicAdd(&g_cursor[sd.y], 1u);
    g_sorted[pos] = sd;
}

// ===========================================================================
// Node kernel: PQ[n] = [ x@(W1a-W1b)+b1 | x@W1b ],  x = [feat(64) | xyz(3)]
// ===========================================================================
__global__ __launch_bounds__(256) void node_pq_kernel(
    const float* __restrict__ xyz, const float* __restrict__ feat,
    const float* __restrict__ W1, const float* __restrict__ b1, int N) {
    __shared__ float ws[67][128];
    __shared__ float xs[32][68];

    int tid = threadIdx.x;
    for (int i = tid; i < 67 * 128; i += 256) {
        int k = i >> 7, c = i & 127;
        float w1b = W1[(k + 67) * 64 + (c & 63)];
        ws[k][c] = (c < 64) ? (W1[k * 64 + c] - w1b) : w1b;
    }
    int n0 = blockIdx.x * 32;
    for (int i = tid; i < 32 * 67; i += 256) {
        int n = i / 67, k = i - n * 67;
        int gn = n0 + n;
        float v = 0.f;
        if (gn < N) v = (k < 64) ? feat[(size_t)gn * 64 + k]
                                 : xyz[(size_t)gn * 3 + (k - 64)];
        xs[n][k] = v;
    }
    __syncthreads();

    int cg = tid & 31, ng = tid >> 5;
    int c0 = cg * 4, nr = ng * 4;
    float acc[4][4];
#pragma unroll
    for (int i = 0; i < 4; i++)
#pragma unroll
        for (int j = 0; j < 4; j++)
            acc[i][j] = (c0 < 64) ? b1[c0 + j] : 0.f;

#pragma unroll 67
    for (int k = 0; k < 67; k++) {
        float4 w = *(const float4*)&ws[k][c0];
#pragma unroll
        for (int i = 0; i < 4; i++) {
            float xv = xs[nr + i][k];
            acc[i][0] = fmaf(xv, w.x, acc[i][0]);
            acc[i][1] = fmaf(xv, w.y, acc[i][1]);
            acc[i][2] = fmaf(xv, w.z, acc[i][2]);
            acc[i][3] = fmaf(xv, w.w, acc[i][3]);
        }
    }
#pragma unroll
    for (int i = 0; i < 4; i++) {
        int gn = n0 + nr + i;
        if (gn < N) {
            float4 v = make_float4(acc[i][0], acc[i][1], acc[i][2], acc[i][3]);
            *(float4*)&g_PQ[(size_t)gn * 128 + c0] = v;
        }
    }
}

// ===========================================================================
// Init output to -inf bits (vectorized); finalize -inf -> 0
// ===========================================================================
__global__ void init_kernel(uint4* __restrict__ out, int n4) {
    int i = blockIdx.x * blockDim.x + threadIdx.x;
    if (i < n4)
        out[i] = make_uint4(0xff800000u, 0xff800000u, 0xff800000u, 0xff800000u);
}

__global__ void finalize_kernel(uint4* __restrict__ out, int n4) {
    int i = blockIdx.x * blockDim.x + threadIdx.x;
    if (i >= n4) return;
    uint4 v = out[i];
    bool ch = false;
    if (v.x == 0xff800000u) { v.x = 0u; ch = true; }
    if (v.y == 0xff800000u) { v.y = 0u; ch = true; }
    if (v.z == 0xff800000u) { v.z = 0u; ch = true; }
    if (v.w == 0xff800000u) { v.w = 0u; ch = true; }
    if (ch) out[i] = v;
}

// ===========================================================================
// Float atomic max via int/uint ordering trick (no return -> RED).
// ===========================================================================
__device__ __forceinline__ void atomic_max_f(float* a, float v) {
    if (v >= 0.f)
        atomicMax((int*)a, __float_as_int(v));
    else
        atomicMin((unsigned int*)a, __float_as_uint(v));
}

// ===========================================================================
// Edge HMMA kernel, v6: dst-sorted edges + CONTIGUOUS warp chunks +
// register segmented reduction. 128 threads = 4 warps, 4 CTAs/SM.
// Contiguous chunks make a node's edges live in ONE warp: P[dst] gathers and
// g_sorted reads become cache-resident, and each node-run emits few REDs.
// Per warp-tile (32 sorted edges):
//   cooperative gather -> z = relu(P[dst]+Q[src]) -> fp16 hi/lo -> SMEM
//   Y = zh@W + zl@W  (mma.sync m16n8k16 f16, fp32 accum, b2 in C-init)
//   Epilogue: ballot-delimited dst-segments reduced in registers (masked max
//   + 3-step shfl.xor butterfly), ONE RED per (segment, col). No out[] reads.
// ===========================================================================
__global__ __launch_bounds__(128, 4) void edge_mma_kernel(
    const float* __restrict__ W2, const float* __restrict__ b2,
    float* __restrict__ out, int E) {
    __shared__ char zbuf[4][8192];  // per warp: zh 4KB + zl 4KB
    __shared__ char wtile[8192];    // W2^T fp16 (64 rows n x 128B k)

    const int tid = threadIdx.x;
    const int lane = tid & 31;
    const int wid = tid >> 5;

    // ---- build swizzled W2^T fp16 in SMEM (once per CTA) ----
    for (int i = tid; i < 64 * 64; i += 128) {
        int n = i >> 6, k = i & 63;
        float w = W2[k * 64 + n];
        uint32_t off = (uint32_t)n * 128 + (((uint32_t)(2 * k)) ^ ((uint32_t)(n & 7) << 4));
        *(__half*)(&wtile[off]) = __float2half_rn(w);
    }
    __syncthreads();

    const uint32_t zh_base = smem_u32(&zbuf[wid][0]);
    const uint32_t zl_base = zh_base + 4096;
    const uint32_t w_base = smem_u32(&wtile[0]);

    // B-frag ldmatrix lane addressing (covers ks pair per x4)
    const uint32_t brow = lane & 7;
    const uint32_t bswz = brow << 4;
    const uint32_t bpart = (((uint32_t)lane >> 3) & 1) * 16 + (((uint32_t)lane >> 4) & 1) * 32;
    const uint32_t boff0 = brow * 128 + (bpart ^ bswz);        // ks0,ks1
    const uint32_t boff1 = brow * 128 + ((bpart + 64) ^ bswz); // ks2,ks3

    // A-frag ldmatrix lane addressing
    const int am = lane >> 3, rowin = lane & 7;
    const uint32_t lswz = (uint32_t)rowin << 4;
    const uint32_t akb = (uint32_t)((am >> 1) << 4);
    const int arow_in = ((am & 1) << 3) + rowin;

    const int rsel = lane >> 2;
    const int colb = (lane & 3) * 2;

    // b2 pairs register-resident
    float2 b2v[8];
#pragma unroll
    for (int nt = 0; nt < 8; nt++)
        b2v[nt] = *(const float2*)(b2 + nt * 8 + colb);

    // cooperative-gather lane pieces
    const int sub = lane >> 4;               // which edge of the pair
    const int cq = lane & 15;                // column quad (4 floats)
    const uint32_t cbyte = (uint32_t)cq * 8; // byte offset in fp16 row

    const float NEG_INF = __int_as_float(0xff800000);

    // ---- contiguous chunk assignment ----
    const int T = (E + 31) >> 5;
    const int nwarp = gridDim.x * 4;
    const int gw = blockIdx.x * 4 + wid;
    const int chunk = (T + nwarp - 1) / nwarp;
    int t = gw * chunk;
    const int tend = (t + chunk < T) ? t + chunk : T;
    if (t >= tend) return;

    int e0 = t * 32 + lane;
    int2 sd = g_sorted[(e0 < E) ? e0 : 0];

    for (; t < tend; t++) {
        int e = t * 32 + lane;
        bool valid = (e < E);
        int mydst = valid ? sd.y : -1;

        // segment boundaries (dst-sorted: equal dst are contiguous)
        unsigned vmask = __ballot_sync(FULLM, valid);
        int prevd = __shfl_up_sync(FULLM, mydst, 1);
        bool flag = valid && (lane == 0 || mydst != prevd);
        unsigned segb = __ballot_sync(FULLM, flag);

        __syncwarp();  // prior tile's ldmatrix reads done before overwrite

        // ---- cooperative gather + relu + fp16 hi/lo split -> SMEM ----
#pragma unroll 4
        for (int g = 0; g < 16; g++) {
            int esel = 2 * g + sub;
            int d = __shfl_sync(FULLM, sd.y, esel);
            int s = __shfl_sync(FULLM, sd.x, esel);
            float4 p = *((const float4*)(g_PQ + (size_t)d * 128) + cq);
            float4 q = *((const float4*)(g_PQ + (size_t)s * 128 + 64) + cq);
            float z0 = fmaxf(p.x + q.x, 0.f), z1 = fmaxf(p.y + q.y, 0.f);
            float z2 = fmaxf(p.z + q.z, 0.f), z3 = fmaxf(p.w + q.w, 0.f);
            __half2 h01 = __floats2half2_rn(z0, z1);
            __half2 h23 = __floats2half2_rn(z2, z3);
            float2 f01 = __half22float2(h01);
            float2 f23 = __half22float2(h23);
            __half2 l01 = __floats2half2_rn(z0 - f01.x, z1 - f01.y);
            __half2 l23 = __floats2half2_rn(z2 - f23.x, z3 - f23.y);
            uint32_t row = (uint32_t)(2 * g + sub);
            uint32_t off = row * 128 + (cbyte ^ ((row & 7) << 4));
            asm volatile("st.shared.v2.b32 [%0], {%1,%2};"
                         :: "r"(zh_base + off),
                            "r"(*(uint32_t*)&h01), "r"(*(uint32_t*)&h23));
            asm volatile("st.shared.v2.b32 [%0], {%1,%2};"
                         :: "r"(zl_base + off),
                            "r"(*(uint32_t*)&l01), "r"(*(uint32_t*)&l23));
        }
        __syncwarp();

        // ---- prefetch next tile's edge record (sequential; hides latency) ----
        if (t + 1 < tend) {
            int en = (t + 1) * 32 + lane;
            sd = g_sorted[(en < E) ? en : 0];
        }

#pragma unroll
        for (int mt = 0; mt < 2; mt++) {
            // A fragments for this 16-row slice (zh + zl, 4 k-steps)
            uint32_t ah[4][4], al[4][4];
            uint32_t rowb = (uint32_t)(mt * 16 + arow_in) * 128;
#pragma unroll
            for (int ks = 0; ks < 4; ks++) {
                uint32_t off = rowb + (((uint32_t)ks * 32 + akb) ^ lswz);
                ldmatrix_x4(ah[ks], zh_base + off);
                ldmatrix_x4(al[ks], zl_base + off);
            }

            // dst of this lane's two fragment rows
            int d0 = __shfl_sync(FULLM, mydst, mt * 16 + rsel);
            int d1 = __shfl_sync(FULLM, mydst, mt * 16 + 8 + rsel);

            // segments overlapping this mt half
            unsigned mtseg;
            if (mt == 0) {
                mtseg = segb & 0xFFFFu;
            } else {
                mtseg = segb & 0xFFFF0000u;
                unsigned lo = segb & 0xFFFFu;
                bool l16v = (vmask >> 16) & 1u;
                bool l16s = (segb >> 16) & 1u;
                if (l16v && !l16s && lo)
                    mtseg |= (1u << (31 - __clz(lo)));  // straddling segment
            }

#pragma unroll
            for (int nt = 0; nt < 8; nt++) {
                uint32_t bw[4][2];
                uint32_t wb = (uint32_t)nt * 1024;
                ldmatrix_x4(&bw[0][0], w_base + wb + boff0);
                ldmatrix_x4(&bw[2][0], w_base + wb + boff1);

                float c[4] = {b2v[nt].x, b2v[nt].y, b2v[nt].x, b2v[nt].y};
#pragma unroll
                for (int ks = 0; ks < 4; ks++) mma16816(c, ah[ks], bw[ks]);
#pragma unroll
                for (int ks = 0; ks < 4; ks++) mma16816(c, al[ks], bw[ks]);

                // ---- register segmented max + one RED per (segment,col) ----
                unsigned b = mtseg;
                while (b) {
                    int sl = __ffs(b) - 1;
                    b &= b - 1;
                    int D = __shfl_sync(FULLM, mydst, sl);
                    float m0 = NEG_INF, m1 = NEG_INF;
                    if (d0 == D) { m0 = c[0]; m1 = c[1]; }
                    if (d1 == D) { m0 = fmaxf(m0, c[2]); m1 = fmaxf(m1, c[3]); }
#pragma unroll
                    for (int o = 4; o <= 16; o <<= 1) {
                        m0 = fmaxf(m0, __shfl_xor_sync(FULLM, m0, o));
                        m1 = fmaxf(m1, __shfl_xor_sync(FULLM, m1, o));
                    }
                    if (lane < 4 && __float_as_uint(m0) != 0xff800000u) {
                        float* o = out + (size_t)D * 64 + nt * 8 + lane * 2;
                        atomic_max_f(o, m0);
                        atomic_max_f(o + 1, m1);
                    }
                }
            }
        }
    }
}

// ===========================================================================
// Inputs: [0]=xyz (N*3 f32), [1]=feat (N*64 f32), [2]=edge_index (2*E int),
//         [3]=W1 (134*64 f32), [4]=b1 (64), [5]=W2 (64*64), [6]=b2 (64)
// ===========================================================================
extern "C" void kernel_launch(void* const* d_in, const int* in_sizes, int n_in,
                              void* d_out, int out_size) {
    const float* xyz  = (const float*)d_in[0];
    const float* feat = (const float*)d_in[1];
    const void*  eidx = d_in[2];
    const float* W1   = (const float*)d_in[3];
    const float* b1   = (const float*)d_in[4];
    const float* W2   = (const float*)d_in[5];
    const float* b2   = (const float*)d_in[6];
    float* out = (float*)d_out;

    int N = in_sizes[0] / 3;
    int E = in_sizes[2] / 2;
    int outn = N * 64;
    int n4 = outn / 4;
    int nb = (N + 1023) / 1024;

    detect_kernel<<<1, 1024>>>((const unsigned int*)eidx);
    zero_hist_kernel<<<(N + 255) / 256, 256>>>(N);
    convhist_kernel<<<(E + 255) / 256, 256>>>(eidx, E);
    scan1_kernel<<<nb, 1024>>>(N);
    scan2_kernel<<<1, 128>>>(nb);
    scan3_kernel<<<(N + 255) / 256, 256>>>(N);
    scatter_kernel<<<(E + 255) / 256, 256>>>(E);
    node_pq_kernel<<<(N + 31) / 32, 256>>>(xyz, feat, W1, b1, N);
    init_kernel<<<(n4 + 255) / 256, 256>>>((uint4*)out, n4);

    int Twarp = (E + 31) >> 5;
    int grid = 4 * 148;  // persistent, 4 CTAs/SM
    if (grid > (Twarp + 3) / 4) grid = (Twarp + 3) / 4;
    edge_mma_kernel<<<grid, 128>>>(W2, b2, out, E);

    finalize_kernel<<<(n4 + 255) / 256, 256>>>((uint4*)out, n4);
}

// round 11
// speedup vs baseline: 1.5494x; 1.3750x over previous
#include <cuda_runtime.h>
#include <cuda_fp16.h>
#include <math.h>
#include <stdint.h>

#define NMAX 100000
#define EMAX 1700000
#define FULLM 0xffffffffu

// Scratch: per-node P (cols 0..63, includes b1) and Q (cols 64..127). 51.2 MB.
__device__ float g_PQ[(size_t)NMAX * 128];
__device__ int2 g_edges[EMAX];    // packed (src, dst), input order
__device__ int2 g_sorted[EMAX];   // grouped by dst
__device__ unsigned g_hist[NMAX];
__device__ unsigned g_cursor[NMAX];
__device__ unsigned g_blocksum[128];
__device__ int g_is64;

__device__ __forceinline__ uint32_t smem_u32(const void* p) {
    uint32_t a;
    asm("{ .reg .u64 t; cvta.to.shared.u64 t, %1; cvt.u32.u64 %0, t; }"
        : "=r"(a) : "l"(p));
    return a;
}

// m16n8k16 row.col f32 += f16*f16
__device__ __forceinline__ void mma16816(float* c, const uint32_t* a,
                                         const uint32_t* b) {
    asm volatile(
        "mma.sync.aligned.m16n8k16.row.col.f32.f16.f16.f32 "
        "{%0,%1,%2,%3}, {%4,%5,%6,%7}, {%8,%9}, {%0,%1,%2,%3};"
        : "+f"(c[0]), "+f"(c[1]), "+f"(c[2]), "+f"(c[3])
        : "r"(a[0]), "r"(a[1]), "r"(a[2]), "r"(a[3]), "r"(b[0]), "r"(b[1]));
}

__device__ __forceinline__ void ldmatrix_x4(uint32_t* r, uint32_t addr) {
    asm volatile(
        "ldmatrix.sync.aligned.m8n8.x4.shared.b16 {%0,%1,%2,%3}, [%4];"
        : "=r"(r[0]), "=r"(r[1]), "=r"(r[2]), "=r"(r[3]) : "r"(addr));
}

// ===========================================================================
// Detect int64 vs int32 edge_index (jax x64-disabled emits int32).
// ===========================================================================
__global__ void detect_kernel(const unsigned int* __restrict__ ei) {
    __shared__ int any;
    if (threadIdx.x == 0) any = 0;
    __syncthreads();
    if (ei[2 * threadIdx.x + 1] != 0u) any = 1;  // benign race
    __syncthreads();
    if (threadIdx.x == 0) g_is64 = (any == 0) ? 1 : 0;
}

__global__ void zero_hist_kernel(int N) {
    int i = blockIdx.x * blockDim.x + threadIdx.x;
    if (i < N) g_hist[i] = 0u;
}

// Fused: edge_index (either width) -> packed int2, + dst histogram.
__global__ void convhist_kernel(const void* __restrict__ eidx, int E) {
    int i = blockIdx.x * blockDim.x + threadIdx.x;
    if (i >= E) return;
    int s, d;
    if (g_is64) {
        const long long* e64 = (const long long*)eidx;
        s = (int)e64[i];
        d = (int)e64[E + i];
    } else {
        const int* e32 = (const int*)eidx;
        s = e32[i];
        d = e32[E + i];
    }
    g_edges[i] = make_int2(s, d);
    atomicAdd(&g_hist[d], 1u);
}

// ===========================================================================
// Multi-block exclusive scan of g_hist -> g_cursor (3 passes).
// ===========================================================================
__global__ __launch_bounds__(1024) void scan1_kernel(int N) {
    __shared__ unsigned wsum[32];
    int tid = threadIdx.x, lane = tid & 31, w = tid >> 5;
    int i = blockIdx.x * 1024 + tid;
    unsigned v = (i < N) ? g_hist[i] : 0u;
    unsigned x = v;
#pragma unroll
    for (int o = 1; o < 32; o <<= 1) {
        unsigned y = __shfl_up_sync(FULLM, x, o);
        if (lane >= o) x += y;
    }
    if (lane == 31) wsum[w] = x;
    __syncthreads();
    if (w == 0) {
        unsigned s = wsum[lane];
#pragma unroll
        for (int o = 1; o < 32; o <<= 1) {
            unsigned y = __shfl_up_sync(FULLM, s, o);
            if (lane >= o) s += y;
        }
        wsum[lane] = s;
    }
    __syncthreads();
    unsigned incl = x + (w > 0 ? wsum[w - 1] : 0u);
    if (i < N) g_cursor[i] = incl - v;  // exclusive within block
    if (tid == 1023) g_blocksum[blockIdx.x] = incl;
}

// Single small block: exclusive scan of <=128 block sums in place.
__global__ void scan2_kernel(int nb) {
    __shared__ unsigned ws[4];
    int tid = threadIdx.x, lane = tid & 31, w = tid >> 5;
    unsigned v = (tid < nb) ? g_blocksum[tid] : 0u;
    unsigned x = v;
#pragma unroll
    for (int o = 1; o < 32; o <<= 1) {
        unsigned y = __shfl_up_sync(FULLM, x, o);
        if (lane >= o) x += y;
    }
    if (lane == 31) ws[w] = x;
    __syncthreads();
    unsigned add = 0;
    for (int j = 0; j < w; j++) add += ws[j];
    if (tid < nb) g_blocksum[tid] = x + add - v;  // exclusive
}

__global__ void scan3_kernel(int N) {
    int i = blockIdx.x * blockDim.x + threadIdx.x;
    if (i < N) g_cursor[i] += g_blocksum[i >> 10];
}

__global__ void scatter_kernel(int E) {
    int i = blockIdx.x * blockDim.x + threadIdx.x;
    if (i >= E) return;
    int2 sd = g_edges[i];
    unsigned pos = atomicAdd(&g_cursor[sd.y], 1u);
    g_sorted[pos] = sd;
}

// ===========================================================================
// Node kernel: PQ[n] = [ x@(W1a-W1b)+b1 | x@W1b ],  x = [feat(64) | xyz(3)]
// ===========================================================================
__global__ __launch_bounds__(256) void node_pq_kernel(
    const float* __restrict__ xyz, const float* __restrict__ feat,
    const float* __restrict__ W1, const float* __restrict__ b1, int N) {
    __shared__ float ws[67][128];
    __shared__ float xs[32][68];

    int tid = threadIdx.x;
    for (int i = tid; i < 67 * 128; i += 256) {
        int k = i >> 7, c = i & 127;
        float w1b = W1[(k + 67) * 64 + (c & 63)];
        ws[k][c] = (c < 64) ? (W1[k * 64 + c] - w1b) : w1b;
    }
    int n0 = blockIdx.x * 32;
    for (int i = tid; i < 32 * 67; i += 256) {
        int n = i / 67, k = i - n * 67;
        int gn = n0 + n;
        float v = 0.f;
        if (gn < N) v = (k < 64) ? feat[(size_t)gn * 64 + k]
                                 : xyz[(size_t)gn * 3 + (k - 64)];
        xs[n][k] = v;
    }
    __syncthreads();

    int cg = tid & 31, ng = tid >> 5;
    int c0 = cg * 4, nr = ng * 4;
    float acc[4][4];
#pragma unroll
    for (int i = 0; i < 4; i++)
#pragma unroll
        for (int j = 0; j < 4; j++)
            acc[i][j] = (c0 < 64) ? b1[c0 + j] : 0.f;

#pragma unroll 67
    for (int k = 0; k < 67; k++) {
        float4 w = *(const float4*)&ws[k][c0];
#pragma unroll
        for (int i = 0; i < 4; i++) {
            float xv = xs[nr + i][k];
            acc[i][0] = fmaf(xv, w.x, acc[i][0]);
            acc[i][1] = fmaf(xv, w.y, acc[i][1]);
            acc[i][2] = fmaf(xv, w.z, acc[i][2]);
            acc[i][3] = fmaf(xv, w.w, acc[i][3]);
        }
    }
#pragma unroll
    for (int i = 0; i < 4; i++) {
        int gn = n0 + nr + i;
        if (gn < N) {
            float4 v = make_float4(acc[i][0], acc[i][1], acc[i][2], acc[i][3]);
            *(float4*)&g_PQ[(size_t)gn * 128 + c0] = v;
        }
    }
}

// ===========================================================================
// Init output to -inf bits (vectorized).
// Finalize: -inf -> 0 (no incoming edges), else add b2[col] (bias commutes
// with max, so it is applied once here instead of per-edge).
// ===========================================================================
__global__ void init_kernel(uint4* __restrict__ out, int n4) {
    int i = blockIdx.x * blockDim.x + threadIdx.x;
    if (i < n4)
        out[i] = make_uint4(0xff800000u, 0xff800000u, 0xff800000u, 0xff800000u);
}

__global__ void finalize_kernel(uint4* __restrict__ out,
                                const float* __restrict__ b2, int n4) {
    int i = blockIdx.x * blockDim.x + threadIdx.x;
    if (i >= n4) return;
    uint4 v = out[i];
    float4 b = ((const float4*)b2)[i & 15];  // 16 uint4 per 64-col row
    float4 r;
    r.x = (v.x == 0xff800000u) ? 0.f : __uint_as_float(v.x) + b.x;
    r.y = (v.y == 0xff800000u) ? 0.f : __uint_as_float(v.y) + b.y;
    r.z = (v.z == 0xff800000u) ? 0.f : __uint_as_float(v.z) + b.z;
    r.w = (v.w == 0xff800000u) ? 0.f : __uint_as_float(v.w) + b.w;
    *(float4*)&out[i] = r;
}

// ===========================================================================
// Float atomic max via int/uint ordering trick (no return -> RED).
// ===========================================================================
__device__ __forceinline__ void atomic_max_f(float* a, float v) {
    if (v >= 0.f)
        atomicMax((int*)a, __float_as_int(v));
    else
        atomicMin((unsigned int*)a, __float_as_uint(v));
}

// ===========================================================================
// Edge HMMA kernel, v7: dst-sorted + contiguous chunks + SMEM-transpose
// epilogue with cross-tile running max. 128 threads = 4 warps, 4 CTAs/SM.
// Per warp-tile (32 sorted edges):
//   cooperative gather -> z = relu(P[dst]+Q[src]) -> fp16 hi/lo -> SMEM
//   A-frags for BOTH mt loaded up-front (frees z-buffer), then per nt:
//   B-frag once, MMAs for both mt (C-init = 0; bias applied in finalize),
//   C fragments stored to the freed z-buffer (XOR-swizzled, conflict-free).
//   Reduction: serial 32-row sweep; lane owns cols {2*lane, 2*lane+1},
//   running (curD, m0, m1) carried ACROSS tiles (chunk is contiguous in
//   sorted order); one RED pair per lane only at dst boundaries.
// ===========================================================================
__global__ __launch_bounds__(128, 4) void edge_mma_kernel(
    const float* __restrict__ W2, float* __restrict__ out, int E) {
    __shared__ char zbuf[4][8192];  // per warp: zh 4KB + zl 4KB; reused as C
    __shared__ char wtile[8192];    // W2^T fp16 (64 rows n x 128B k)

    const int tid = threadIdx.x;
    const int lane = tid & 31;
    const int wid = tid >> 5;

    // ---- build swizzled W2^T fp16 in SMEM (once per CTA) ----
    for (int i = tid; i < 64 * 64; i += 128) {
        int n = i >> 6, k = i & 63;
        float w = W2[k * 64 + n];
        uint32_t off = (uint32_t)n * 128 + (((uint32_t)(2 * k)) ^ ((uint32_t)(n & 7) << 4));
        *(__half*)(&wtile[off]) = __float2half_rn(w);
    }
    __syncthreads();

    const uint32_t zh_base = smem_u32(&zbuf[wid][0]);
    const uint32_t zl_base = zh_base + 4096;
    const uint32_t cbase = zh_base;  // C[32][64] f32 reuses the z-buffer
    const uint32_t w_base = smem_u32(&wtile[0]);

    // B-frag ldmatrix lane addressing (covers ks pair per x4)
    const uint32_t brow = lane & 7;
    const uint32_t bswz = brow << 4;
    const uint32_t bpart = (((uint32_t)lane >> 3) & 1) * 16 + (((uint32_t)lane >> 4) & 1) * 32;
    const uint32_t boff0 = brow * 128 + (bpart ^ bswz);        // ks0,ks1
    const uint32_t boff1 = brow * 128 + ((bpart + 64) ^ bswz); // ks2,ks3

    // A-frag ldmatrix lane addressing
    const int am = lane >> 3, rowin = lane & 7;
    const uint32_t lswz = (uint32_t)rowin << 4;
    const uint32_t akb = (uint32_t)((am >> 1) << 4);
    const int arow_in = ((am & 1) << 3) + rowin;

    // C-store lane addressing
    const int crow = lane >> 2;                     // fragment row within 8
    const uint32_t ccb = (uint32_t)(lane & 3) * 8;  // col bytes within n-tile

    // cooperative-gather lane pieces
    const int sub = lane >> 4;               // which edge of the pair
    const int cq = lane & 15;                // column quad (4 floats)
    const uint32_t cbyte = (uint32_t)cq * 8; // byte offset in fp16 row

    // ---- contiguous chunk assignment ----
    const int T = (E + 31) >> 5;
    const int nwarp = gridDim.x * 4;
    const int gw = blockIdx.x * 4 + wid;
    const int chunk = (T + nwarp - 1) / nwarp;
    int t = gw * chunk;
    const int tend = (t + chunk < T) ? t + chunk : T;
    if (t >= tend) return;

    int e0 = t * 32 + lane;
    int2 sd = g_sorted[(e0 < E) ? e0 : 0];

    // running segmented-max state (carried across tiles)
    int curD = -1;
    float m0 = 0.f, m1 = 0.f;

    for (; t < tend; t++) {
        int e = t * 32 + lane;
        bool valid = (e < E);
        int mydst = valid ? sd.y : -1;

        __syncwarp();  // prior tile's C reads done before gather overwrite

        // ---- cooperative gather + relu + fp16 hi/lo split -> SMEM ----
#pragma unroll 4
        for (int g = 0; g < 16; g++) {
            int esel = 2 * g + sub;
            int d = __shfl_sync(FULLM, sd.y, esel);
            int s = __shfl_sync(FULLM, sd.x, esel);
            float4 p = *((const float4*)(g_PQ + (size_t)d * 128) + cq);
            float4 q = *((const float4*)(g_PQ + (size_t)s * 128 + 64) + cq);
            float z0 = fmaxf(p.x + q.x, 0.f), z1 = fmaxf(p.y + q.y, 0.f);
            float z2 = fmaxf(p.z + q.z, 0.f), z3 = fmaxf(p.w + q.w, 0.f);
            __half2 h01 = __floats2half2_rn(z0, z1);
            __half2 h23 = __floats2half2_rn(z2, z3);
            float2 f01 = __half22float2(h01);
            float2 f23 = __half22float2(h23);
            __half2 l01 = __floats2half2_rn(z0 - f01.x, z1 - f01.y);
            __half2 l23 = __floats2half2_rn(z2 - f23.x, z3 - f23.y);
            uint32_t row = (uint32_t)(2 * g + sub);
            uint32_t off = row * 128 + (cbyte ^ ((row & 7) << 4));
            asm volatile("st.shared.v2.b32 [%0], {%1,%2};"
                         :: "r"(zh_base + off),
                            "r"(*(uint32_t*)&h01), "r"(*(uint32_t*)&h23));
            asm volatile("st.shared.v2.b32 [%0], {%1,%2};"
                         :: "r"(zl_base + off),
                            "r"(*(uint32_t*)&l01), "r"(*(uint32_t*)&l23));
        }
        __syncwarp();

        // ---- prefetch next tile's edge record (sequential) ----
        if (t + 1 < tend) {
            int en = (t + 1) * 32 + lane;
            sd = g_sorted[(en < E) ? en : 0];
        }

        // ---- load ALL A fragments up-front (frees z-buffer for C) ----
        uint32_t ah[8][4], al[8][4];  // [mt*4+ks]
#pragma unroll
        for (int mt = 0; mt < 2; mt++) {
            uint32_t rowb = (uint32_t)(mt * 16 + arow_in) * 128;
#pragma unroll
            for (int ks = 0; ks < 4; ks++) {
                uint32_t off = rowb + (((uint32_t)ks * 32 + akb) ^ lswz);
                ldmatrix_x4(ah[mt * 4 + ks], zh_base + off);
                ldmatrix_x4(al[mt * 4 + ks], zl_base + off);
            }
        }
        // In-warp shared ops are processed in program order: the LDSM reads
        // above complete before the C stores below touch the same bytes.

#pragma unroll
        for (int nt = 0; nt < 8; nt++) {
            uint32_t bw[4][2];
            uint32_t wb = (uint32_t)nt * 1024;
            ldmatrix_x4(&bw[0][0], w_base + wb + boff0);
            ldmatrix_x4(&bw[2][0], w_base + wb + boff1);
            uint32_t cb = (uint32_t)nt * 32 + ccb;
#pragma unroll
            for (int mt = 0; mt < 2; mt++) {
                float c[4] = {0.f, 0.f, 0.f, 0.f};
#pragma unroll
                for (int ks = 0; ks < 4; ks++) mma16816(c, ah[mt * 4 + ks], bw[ks]);
#pragma unroll
                for (int ks = 0; ks < 4; ks++) mma16816(c, al[mt * 4 + ks], bw[ks]);

                int r0 = mt * 16 + crow;
                uint32_t sw = (uint32_t)(r0 & 7) << 5;
                uint32_t a0 = cbase + (uint32_t)r0 * 256 + (cb ^ sw);
                asm volatile("st.shared.v2.f32 [%0], {%1,%2};"
                             :: "r"(a0), "f"(c[0]), "f"(c[1]));
                asm volatile("st.shared.v2.f32 [%0], {%1,%2};"
                             :: "r"(a0 + 2048), "f"(c[2]), "f"(c[3]));  // row+8
            }
        }
        __syncwarp();  // all C stores visible before cross-lane reads

        // ---- serial 32-row sweep: running max per col pair, RED at
        //      dst boundaries only ----
#pragma unroll 8
        for (int r = 0; r < 32; r++) {
            int d = __shfl_sync(FULLM, mydst, r);
            uint32_t off = cbase + (uint32_t)r * 256 +
                           (((uint32_t)lane * 8) ^ ((uint32_t)(r & 7) << 5));
            float y0, y1;
            asm volatile("ld.shared.v2.f32 {%0,%1}, [%2];"
                         : "=f"(y0), "=f"(y1) : "r"(off));
            if (d < 0) continue;  // trailing invalid rows
            if (d != curD) {
                if (curD >= 0) {
                    float* o = out + (size_t)curD * 64 + lane * 2;
                    atomic_max_f(o, m0);
                    atomic_max_f(o + 1, m1);
                }
                curD = d;
                m0 = y0;
                m1 = y1;
            } else {
                m0 = fmaxf(m0, y0);
                m1 = fmaxf(m1, y1);
            }
        }
    }

    // ---- final flush ----
    if (curD >= 0) {
        float* o = out + (size_t)curD * 64 + lane * 2;
        atomic_max_f(o, m0);
        atomic_max_f(o + 1, m1);
    }
}

// ===========================================================================
// Inputs: [0]=xyz (N*3 f32), [1]=feat (N*64 f32), [2]=edge_index (2*E int),
//         [3]=W1 (134*64 f32), [4]=b1 (64), [5]=W2 (64*64), [6]=b2 (64)
// ===========================================================================
extern "C" void kernel_launch(void* const* d_in, const int* in_sizes, int n_in,
                              void* d_out, int out_size) {
    const float* xyz  = (const float*)d_in[0];
    const float* feat = (const float*)d_in[1];
    const void*  eidx = d_in[2];
    const float* W1   = (const float*)d_in[3];
    const float* b1   = (const float*)d_in[4];
    const float* W2   = (const float*)d_in[5];
    const float* b2   = (const float*)d_in[6];
    float* out = (float*)d_out;

    int N = in_sizes[0] / 3;
    int E = in_sizes[2] / 2;
    int outn = N * 64;
    int n4 = outn / 4;
    int nb = (N + 1023) / 1024;

    detect_kernel<<<1, 1024>>>((const unsigned int*)eidx);
    zero_hist_kernel<<<(N + 255) / 256, 256>>>(N);
    convhist_kernel<<<(E + 255) / 256, 256>>>(eidx, E);
    scan1_kernel<<<nb, 1024>>>(N);
    scan2_kernel<<<1, 128>>>(nb);
    scan3_kernel<<<(N + 255) / 256, 256>>>(N);
    scatter_kernel<<<(E + 255) / 256, 256>>>(E);
    node_pq_kernel<<<(N + 31) / 32, 256>>>(xyz, feat, W1, b1, N);
    init_kernel<<<(n4 + 255) / 256, 256>>>((uint4*)out, n4);

    int Twarp = (E + 31) >> 5;
    int grid = 4 * 148;  // persistent, 4 CTAs/SM
    if (grid > (Twarp + 3) / 4) grid = (Twarp + 3) / 4;
    edge_mma_kernel<<<grid, 128>>>(W2, out, E);

    finalize_kernel<<<(n4 + 255) / 256, 256>>>((uint4*)out, b2, n4);
}

// round 12
// speedup vs baseline: 1.6619x; 1.0726x over previous
#include <cuda_runtime.h>
#include <cuda_fp16.h>
#include <math.h>
#include <stdint.h>

#define NMAX 100000
#define EMAX 1700000
#define FULLM 0xffffffffu

// Scratch: per-node P (cols 0..63, includes b1) and Q (cols 64..127). 51.2 MB.
__device__ float g_PQ[(size_t)NMAX * 128];
__device__ int2 g_edges[EMAX];    // packed (src, dst), input order
__device__ int2 g_sorted[EMAX];   // grouped by dst
__device__ unsigned g_hist[NMAX];
__device__ unsigned g_cursor[NMAX];
__device__ unsigned g_blocksum[128];
__device__ int g_is64;

__device__ __forceinline__ uint32_t smem_u32(const void* p) {
    uint32_t a;
    asm("{ .reg .u64 t; cvta.to.shared.u64 t, %1; cvt.u32.u64 %0, t; }"
        : "=r"(a) : "l"(p));
    return a;
}

// m16n8k16 row.col f32 += f16*f16
__device__ __forceinline__ void mma16816(float* c, const uint32_t* a,
                                         const uint32_t* b) {
    asm volatile(
        "mma.sync.aligned.m16n8k16.row.col.f32.f16.f16.f32 "
        "{%0,%1,%2,%3}, {%4,%5,%6,%7}, {%8,%9}, {%0,%1,%2,%3};"
        : "+f"(c[0]), "+f"(c[1]), "+f"(c[2]), "+f"(c[3])
        : "r"(a[0]), "r"(a[1]), "r"(a[2]), "r"(a[3]), "r"(b[0]), "r"(b[1]));
}

__device__ __forceinline__ void ldmatrix_x4(uint32_t* r, uint32_t addr) {
    asm volatile(
        "ldmatrix.sync.aligned.m8n8.x4.shared.b16 {%0,%1,%2,%3}, [%4];"
        : "=r"(r[0]), "=r"(r[1]), "=r"(r[2]), "=r"(r[3]) : "r"(addr));
}

// ===========================================================================
// Prep: zero dst-histogram (all blocks) + detect int64 vs int32 edge_index
// (block 0 only; jax x64-disabled emits int32).
// ===========================================================================
__global__ __launch_bounds__(1024) void prep_kernel(
    const unsigned int* __restrict__ ei, int N) {
    int i = blockIdx.x * 1024 + threadIdx.x;
    if (i < N) g_hist[i] = 0u;
    if (blockIdx.x == 0) {
        __shared__ int any;
        if (threadIdx.x == 0) any = 0;
        __syncthreads();
        if (ei[2 * threadIdx.x + 1] != 0u) any = 1;  // benign race
        __syncthreads();
        if (threadIdx.x == 0) g_is64 = (any == 0) ? 1 : 0;
    }
}

// Fused: edge_index (either width) -> packed int2, + dst histogram.
__global__ void convhist_kernel(const void* __restrict__ eidx, int E) {
    int i = blockIdx.x * blockDim.x + threadIdx.x;
    if (i >= E) return;
    int s, d;
    if (g_is64) {
        const long long* e64 = (const long long*)eidx;
        s = (int)e64[i];
        d = (int)e64[E + i];
    } else {
        const int* e32 = (const int*)eidx;
        s = e32[i];
        d = e32[E + i];
    }
    g_edges[i] = make_int2(s, d);
    atomicAdd(&g_hist[d], 1u);
}

// ===========================================================================
// Multi-block exclusive scan of g_hist -> g_cursor (3 passes).
// ===========================================================================
__global__ __launch_bounds__(1024) void scan1_kernel(int N) {
    __shared__ unsigned wsum[32];
    int tid = threadIdx.x, lane = tid & 31, w = tid >> 5;
    int i = blockIdx.x * 1024 + tid;
    unsigned v = (i < N) ? g_hist[i] : 0u;
    unsigned x = v;
#pragma unroll
    for (int o = 1; o < 32; o <<= 1) {
        unsigned y = __shfl_up_sync(FULLM, x, o);
        if (lane >= o) x += y;
    }
    if (lane == 31) wsum[w] = x;
    __syncthreads();
    if (w == 0) {
        unsigned s = wsum[lane];
#pragma unroll
        for (int o = 1; o < 32; o <<= 1) {
            unsigned y = __shfl_up_sync(FULLM, s, o);
            if (lane >= o) s += y;
        }
        wsum[lane] = s;
    }
    __syncthreads();
    unsigned incl = x + (w > 0 ? wsum[w - 1] : 0u);
    if (i < N) g_cursor[i] = incl - v;  // exclusive within block
    if (tid == 1023) g_blocksum[blockIdx.x] = incl;
}

// Single small block: exclusive scan of <=128 block sums in place.
__global__ void scan2_kernel(int nb) {
    __shared__ unsigned ws[4];
    int tid = threadIdx.x, lane = tid & 31, w = tid >> 5;
    unsigned v = (tid < nb) ? g_blocksum[tid] : 0u;
    unsigned x = v;
#pragma unroll
    for (int o = 1; o < 32; o <<= 1) {
        unsigned y = __shfl_up_sync(FULLM, x, o);
        if (lane >= o) x += y;
    }
    if (lane == 31) ws[w] = x;
    __syncthreads();
    unsigned add = 0;
    for (int j = 0; j < w; j++) add += ws[j];
    if (tid < nb) g_blocksum[tid] = x + add - v;  // exclusive
}

__global__ void scan3_kernel(int N) {
    int i = blockIdx.x * blockDim.x + threadIdx.x;
    if (i < N) g_cursor[i] += g_blocksum[i >> 10];
}

__global__ void scatter_kernel(int E) {
    int i = blockIdx.x * blockDim.x + threadIdx.x;
    if (i >= E) return;
    int2 sd = g_edges[i];
    unsigned pos = atomicAdd(&g_cursor[sd.y], 1u);
    g_sorted[pos] = sd;
}

// ===========================================================================
// Node kernel: PQ[n] = [ x@(W1a-W1b)+b1 | x@W1b ],  x = [feat(64) | xyz(3)]
// ===========================================================================
__global__ __launch_bounds__(256) void node_pq_kernel(
    const float* __restrict__ xyz, const float* __restrict__ feat,
    const float* __restrict__ W1, const float* __restrict__ b1, int N) {
    __shared__ float ws[67][128];
    __shared__ float xs[32][68];

    int tid = threadIdx.x;
    for (int i = tid; i < 67 * 128; i += 256) {
        int k = i >> 7, c = i & 127;
        float w1b = W1[(k + 67) * 64 + (c & 63)];
        ws[k][c] = (c < 64) ? (W1[k * 64 + c] - w1b) : w1b;
    }
    int n0 = blockIdx.x * 32;
    for (int i = tid; i < 32 * 67; i += 256) {
        int n = i / 67, k = i - n * 67;
        int gn = n0 + n;
        float v = 0.f;
        if (gn < N) v = (k < 64) ? feat[(size_t)gn * 64 + k]
                                 : xyz[(size_t)gn * 3 + (k - 64)];
        xs[n][k] = v;
    }
    __syncthreads();

    int cg = tid & 31, ng = tid >> 5;
    int c0 = cg * 4, nr = ng * 4;
    float acc[4][4];
#pragma unroll
    for (int i = 0; i < 4; i++)
#pragma unroll
        for (int j = 0; j < 4; j++)
            acc[i][j] = (c0 < 64) ? b1[c0 + j] : 0.f;

#pragma unroll 67
    for (int k = 0; k < 67; k++) {
        float4 w = *(const float4*)&ws[k][c0];
#pragma unroll
        for (int i = 0; i < 4; i++) {
            float xv = xs[nr + i][k];
            acc[i][0] = fmaf(xv, w.x, acc[i][0]);
            acc[i][1] = fmaf(xv, w.y, acc[i][1]);
            acc[i][2] = fmaf(xv, w.z, acc[i][2]);
            acc[i][3] = fmaf(xv, w.w, acc[i][3]);
        }
    }
#pragma unroll
    for (int i = 0; i < 4; i++) {
        int gn = n0 + nr + i;
        if (gn < N) {
            float4 v = make_float4(acc[i][0], acc[i][1], acc[i][2], acc[i][3]);
            *(float4*)&g_PQ[(size_t)gn * 128 + c0] = v;
        }
    }
}

// ===========================================================================
// Init output to -inf bits (vectorized).
// Finalize: -inf -> 0 (no incoming edges), else add b2[col] (bias commutes
// with max, so it is applied once here instead of per-edge).
// ===========================================================================
__global__ void init_kernel(uint4* __restrict__ out, int n4) {
    int i = blockIdx.x * blockDim.x + threadIdx.x;
    if (i < n4)
        out[i] = make_uint4(0xff800000u, 0xff800000u, 0xff800000u, 0xff800000u);
}

__global__ void finalize_kernel(uint4* __restrict__ out,
                                const float* __restrict__ b2, int n4) {
    int i = blockIdx.x * blockDim.x + threadIdx.x;
    if (i >= n4) return;
    uint4 v = out[i];
    float4 b = ((const float4*)b2)[i & 15];  // 16 uint4 per 64-col row
    float4 r;
    r.x = (v.x == 0xff800000u) ? 0.f : __uint_as_float(v.x) + b.x;
    r.y = (v.y == 0xff800000u) ? 0.f : __uint_as_float(v.y) + b.y;
    r.z = (v.z == 0xff800000u) ? 0.f : __uint_as_float(v.z) + b.z;
    r.w = (v.w == 0xff800000u) ? 0.f : __uint_as_float(v.w) + b.w;
    *(float4*)&out[i] = r;
}

// ===========================================================================
// Float atomic max via int/uint ordering trick (no return -> RED).
// ===========================================================================
__device__ __forceinline__ void atomic_max_f(float* a, float v) {
    if (v >= 0.f)
        atomicMax((int*)a, __float_as_int(v));
    else
        atomicMin((unsigned int*)a, __float_as_uint(v));
}

// ===========================================================================
// Edge HMMA kernel, v8: single-fp16 z (error budget: W2-fp16 term 1.63e-4
// measured + independent z-fp16 term of same size -> ~2.3e-4 total, 4x
// under threshold). Halves MMAs (64/tile), A-ldmatrix (8/tile), and the
// z conversion/STS work vs v7. Structure otherwise identical to v7:
// dst-sorted + contiguous chunks + SMEM-transpose epilogue with cross-tile
// running max. 128 threads = 4 warps, 4 CTAs/SM.
// ===========================================================================
__global__ __launch_bounds__(128, 4) void edge_mma_kernel(
    const float* __restrict__ W2, float* __restrict__ out, int E) {
    __shared__ char zbuf[4][8192];  // per warp: z 4KB (first half); C 8KB
    __shared__ char wtile[8192];    // W2^T fp16 (64 rows n x 128B k)

    const int tid = threadIdx.x;
    const int lane = tid & 31;
    const int wid = tid >> 5;

    // ---- build swizzled W2^T fp16 in SMEM (once per CTA) ----
    for (int i = tid; i < 64 * 64; i += 128) {
        int n = i >> 6, k = i & 63;
        float w = W2[k * 64 + n];
        uint32_t off = (uint32_t)n * 128 + (((uint32_t)(2 * k)) ^ ((uint32_t)(n & 7) << 4));
        *(__half*)(&wtile[off]) = __float2half_rn(w);
    }
    __syncthreads();

    const uint32_t zh_base = smem_u32(&zbuf[wid][0]);
    const uint32_t cbase = zh_base;  // C[32][64] f32 reuses the buffer
    const uint32_t w_base = smem_u32(&wtile[0]);

    // B-frag ldmatrix lane addressing (covers ks pair per x4)
    const uint32_t brow = lane & 7;
    const uint32_t bswz = brow << 4;
    const uint32_t bpart = (((uint32_t)lane >> 3) & 1) * 16 + (((uint32_t)lane >> 4) & 1) * 32;
    const uint32_t boff0 = brow * 128 + (bpart ^ bswz);        // ks0,ks1
    const uint32_t boff1 = brow * 128 + ((bpart + 64) ^ bswz); // ks2,ks3

    // A-frag ldmatrix lane addressing
    const int am = lane >> 3, rowin = lane & 7;
    const uint32_t lswz = (uint32_t)rowin << 4;
    const uint32_t akb = (uint32_t)((am >> 1) << 4);
    const int arow_in = ((am & 1) << 3) + rowin;

    // C-store lane addressing
    const int crow = lane >> 2;                     // fragment row within 8
    const uint32_t ccb = (uint32_t)(lane & 3) * 8;  // col bytes within n-tile

    // cooperative-gather lane pieces
    const int sub = lane >> 4;               // which edge of the pair
    const int cq = lane & 15;                // column quad (4 floats)
    const uint32_t cbyte = (uint32_t)cq * 8; // byte offset in fp16 row

    // ---- contiguous chunk assignment ----
    const int T = (E + 31) >> 5;
    const int nwarp = gridDim.x * 4;
    const int gw = blockIdx.x * 4 + wid;
    const int chunk = (T + nwarp - 1) / nwarp;
    int t = gw * chunk;
    const int tend = (t + chunk < T) ? t + chunk : T;
    if (t >= tend) return;

    int e0 = t * 32 + lane;
    int2 sd = g_sorted[(e0 < E) ? e0 : 0];

    // running segmented-max state (carried across tiles)
    int curD = -1;
    float m0 = 0.f, m1 = 0.f;

    for (; t < tend; t++) {
        int e = t * 32 + lane;
        bool valid = (e < E);
        int mydst = valid ? sd.y : -1;

        __syncwarp();  // prior tile's C reads done before gather overwrite

        // ---- cooperative gather + relu + fp16 -> SMEM ----
#pragma unroll 4
        for (int g = 0; g < 16; g++) {
            int esel = 2 * g + sub;
            int d = __shfl_sync(FULLM, sd.y, esel);
            int s = __shfl_sync(FULLM, sd.x, esel);
            float4 p = *((const float4*)(g_PQ + (size_t)d * 128) + cq);
            float4 q = *((const float4*)(g_PQ + (size_t)s * 128 + 64) + cq);
            float z0 = fmaxf(p.x + q.x, 0.f), z1 = fmaxf(p.y + q.y, 0.f);
            float z2 = fmaxf(p.z + q.z, 0.f), z3 = fmaxf(p.w + q.w, 0.f);
            __half2 h01 = __floats2half2_rn(z0, z1);
            __half2 h23 = __floats2half2_rn(z2, z3);
            uint32_t row = (uint32_t)(2 * g + sub);
            uint32_t off = row * 128 + (cbyte ^ ((row & 7) << 4));
            asm volatile("st.shared.v2.b32 [%0], {%1,%2};"
                         :: "r"(zh_base + off),
                            "r"(*(uint32_t*)&h01), "r"(*(uint32_t*)&h23));
        }
        __syncwarp();

        // ---- prefetch next tile's edge record (sequential) ----
        if (t + 1 < tend) {
            int en = (t + 1) * 32 + lane;
            sd = g_sorted[(en < E) ? en : 0];
        }

        // ---- load ALL A fragments up-front (frees z-buffer for C) ----
        uint32_t ah[8][4];  // [mt*4+ks]
#pragma unroll
        for (int mt = 0; mt < 2; mt++) {
            uint32_t rowb = (uint32_t)(mt * 16 + arow_in) * 128;
#pragma unroll
            for (int ks = 0; ks < 4; ks++) {
                uint32_t off = rowb + (((uint32_t)ks * 32 + akb) ^ lswz);
                ldmatrix_x4(ah[mt * 4 + ks], zh_base + off);
            }
        }
        // In-warp shared ops are processed in program order: the LDSM reads
        // above complete before the C stores below touch the same bytes.

#pragma unroll
        for (int nt = 0; nt < 8; nt++) {
            uint32_t bw[4][2];
            uint32_t wb = (uint32_t)nt * 1024;
            ldmatrix_x4(&bw[0][0], w_base + wb + boff0);
            ldmatrix_x4(&bw[2][0], w_base + wb + boff1);
            uint32_t cb = (uint32_t)nt * 32 + ccb;
#pragma unroll
            for (int mt = 0; mt < 2; mt++) {
                float c[4] = {0.f, 0.f, 0.f, 0.f};
#pragma unroll
                for (int ks = 0; ks < 4; ks++) mma16816(c, ah[mt * 4 + ks], bw[ks]);

                int r0 = mt * 16 + crow;
                uint32_t sw = (uint32_t)(r0 & 7) << 5;
                uint32_t a0 = cbase + (uint32_t)r0 * 256 + (cb ^ sw);
                asm volatile("st.shared.v2.f32 [%0], {%1,%2};"
                             :: "r"(a0), "f"(c[0]), "f"(c[1]));
                asm volatile("st.shared.v2.f32 [%0], {%1,%2};"
                             :: "r"(a0 + 2048), "f"(c[2]), "f"(c[3]));  // row+8
            }
        }
        __syncwarp();  // all C stores visible before cross-lane reads

        // ---- serial 32-row sweep: running max per col pair, RED at
        //      dst boundaries only ----
#pragma unroll 8
        for (int r = 0; r < 32; r++) {
            int d = __shfl_sync(FULLM, mydst, r);
            uint32_t off = cbase + (uint32_t)r * 256 +
                           (((uint32_t)lane * 8) ^ ((uint32_t)(r & 7) << 5));
            float y0, y1;
            asm volatile("ld.shared.v2.f32 {%0,%1}, [%2];"
                         : "=f"(y0), "=f"(y1) : "r"(off));
            if (d < 0) continue;  // trailing invalid rows
            if (d != curD) {
                if (curD >= 0) {
                    float* o = out + (size_t)curD * 64 + lane * 2;
                    atomic_max_f(o, m0);
                    atomic_max_f(o + 1, m1);
                }
                curD = d;
                m0 = y0;
                m1 = y1;
            } else {
                m0 = fmaxf(m0, y0);
                m1 = fmaxf(m1, y1);
            }
        }
    }

    // ---- final flush ----
    if (curD >= 0) {
        float* o = out + (size_t)curD * 64 + lane * 2;
        atomic_max_f(o, m0);
        atomic_max_f(o + 1, m1);
    }
}

// ===========================================================================
// Inputs: [0]=xyz (N*3 f32), [1]=feat (N*64 f32), [2]=edge_index (2*E int),
//         [3]=W1 (134*64 f32), [4]=b1 (64), [5]=W2 (64*64), [6]=b2 (64)
// ===========================================================================
extern "C" void kernel_launch(void* const* d_in, const int* in_sizes, int n_in,
                              void* d_out, int out_size) {
    const float* xyz  = (const float*)d_in[0];
    const float* feat = (const float*)d_in[1];
    const void*  eidx = d_in[2];
    const float* W1   = (const float*)d_in[3];
    const float* b1   = (const float*)d_in[4];
    const float* W2   = (const float*)d_in[5];
    const float* b2   = (const float*)d_in[6];
    float* out = (float*)d_out;

    int N = in_sizes[0] / 3;
    int E = in_sizes[2] / 2;
    int outn = N * 64;
    int n4 = outn / 4;
    int nb = (N + 1023) / 1024;

    prep_kernel<<<nb, 1024>>>((const unsigned int*)eidx, N);
    convhist_kernel<<<(E + 255) / 256, 256>>>(eidx, E);
    scan1_kernel<<<nb, 1024>>>(N);
    scan2_kernel<<<1, 128>>>(nb);
    scan3_kernel<<<(N + 255) / 256, 256>>>(N);
    scatter_kernel<<<(E + 255) / 256, 256>>>(E);
    node_pq_kernel<<<(N + 31) / 32, 256>>>(xyz, feat, W1, b1, N);
    init_kernel<<<(n4 + 255) / 256, 256>>>((uint4*)out, n4);

    int Twarp = (E + 31) >> 5;
    int grid = 4 * 148;  // persistent, 4 CTAs/SM
    if (grid > (Twarp + 3) / 4) grid = (Twarp + 3) / 4;
    edge_mma_kernel<<<grid, 128>>>(W2, out, E);

    finalize_kernel<<<(n4 + 255) / 256, 256>>>((uint4*)out, b2, n4);
}

// round 13
// speedup vs baseline: 1.8480x; 1.1120x over previous
#include <cuda_runtime.h>
#include <cuda_fp16.h>
#include <math.h>
#include <stdint.h>

#define NMAX 100000
#define EMAX 1700000
#define FULLM 0xffffffffu

// Scratch: per-node fp16 P (cols 0..63, includes b1) and Q (64..127). 25.6 MB.
__device__ __half g_PQh[(size_t)NMAX * 128];
__device__ int2 g_edges[EMAX];    // packed (src, dst), input order
__device__ int2 g_sorted[EMAX];   // grouped by dst
__device__ unsigned g_hist[NMAX];
__device__ unsigned g_cursor[NMAX];
__device__ unsigned g_blocksum[128];
__device__ int g_is64;

__device__ __forceinline__ uint32_t smem_u32(const void* p) {
    uint32_t a;
    asm("{ .reg .u64 t; cvta.to.shared.u64 t, %1; cvt.u32.u64 %0, t; }"
        : "=r"(a) : "l"(p));
    return a;
}

// m16n8k16 row.col f32 += f16*f16
__device__ __forceinline__ void mma16816(float* c, const uint32_t* a,
                                         const uint32_t* b) {
    asm volatile(
        "mma.sync.aligned.m16n8k16.row.col.f32.f16.f16.f32 "
        "{%0,%1,%2,%3}, {%4,%5,%6,%7}, {%8,%9}, {%0,%1,%2,%3};"
        : "+f"(c[0]), "+f"(c[1]), "+f"(c[2]), "+f"(c[3])
        : "r"(a[0]), "r"(a[1]), "r"(a[2]), "r"(a[3]), "r"(b[0]), "r"(b[1]));
}

__device__ __forceinline__ void ldmatrix_x4(uint32_t* r, uint32_t addr) {
    asm volatile(
        "ldmatrix.sync.aligned.m8n8.x4.shared.b16 {%0,%1,%2,%3}, [%4];"
        : "=r"(r[0]), "=r"(r[1]), "=r"(r[2]), "=r"(r[3]) : "r"(addr));
}

// ===========================================================================
// Prep: zero dst-histogram (all blocks) + detect int64 vs int32 edge_index
// (block 0 only; jax x64-disabled emits int32).
// ===========================================================================
__global__ __launch_bounds__(1024) void prep_kernel(
    const unsigned int* __restrict__ ei, int N) {
    int i = blockIdx.x * 1024 + threadIdx.x;
    if (i < N) g_hist[i] = 0u;
    if (blockIdx.x == 0) {
        __shared__ int any;
        if (threadIdx.x == 0) any = 0;
        __syncthreads();
        if (ei[2 * threadIdx.x + 1] != 0u) any = 1;  // benign race
        __syncthreads();
        if (threadIdx.x == 0) g_is64 = (any == 0) ? 1 : 0;
    }
}

// Fused: edge_index (either width) -> packed int2, + dst histogram.
__global__ void convhist_kernel(const void* __restrict__ eidx, int E) {
    int i = blockIdx.x * blockDim.x + threadIdx.x;
    if (i >= E) return;
    int s, d;
    if (g_is64) {
        const long long* e64 = (const long long*)eidx;
        s = (int)e64[i];
        d = (int)e64[E + i];
    } else {
        const int* e32 = (const int*)eidx;
        s = e32[i];
        d = e32[E + i];
    }
    g_edges[i] = make_int2(s, d);
    atomicAdd(&g_hist[d], 1u);
}

// ===========================================================================
// Multi-block exclusive scan of g_hist (2 passes; block offsets are applied
// inside scatter_kernel, so no third pass).
// ===========================================================================
__global__ __launch_bounds__(1024) void scan1_kernel(int N) {
    __shared__ unsigned wsum[32];
    int tid = threadIdx.x, lane = tid & 31, w = tid >> 5;
    int i = blockIdx.x * 1024 + tid;
    unsigned v = (i < N) ? g_hist[i] : 0u;
    unsigned x = v;
#pragma unroll
    for (int o = 1; o < 32; o <<= 1) {
        unsigned y = __shfl_up_sync(FULLM, x, o);
        if (lane >= o) x += y;
    }
    if (lane == 31) wsum[w] = x;
    __syncthreads();
    if (w == 0) {
        unsigned s = wsum[lane];
#pragma unroll
        for (int o = 1; o < 32; o <<= 1) {
            unsigned y = __shfl_up_sync(FULLM, s, o);
            if (lane >= o) s += y;
        }
        wsum[lane] = s;
    }
    __syncthreads();
    unsigned incl = x + (w > 0 ? wsum[w - 1] : 0u);
    if (i < N) g_cursor[i] = incl - v;  // exclusive within block
    if (tid == 1023) g_blocksum[blockIdx.x] = incl;
}

// Single small block: exclusive scan of <=128 block sums in place.
__global__ void scan2_kernel(int nb) {
    __shared__ unsigned ws[4];
    int tid = threadIdx.x, lane = tid & 31, w = tid >> 5;
    unsigned v = (tid < nb) ? g_blocksum[tid] : 0u;
    unsigned x = v;
#pragma unroll
    for (int o = 1; o < 32; o <<= 1) {
        unsigned y = __shfl_up_sync(FULLM, x, o);
        if (lane >= o) x += y;
    }
    if (lane == 31) ws[w] = x;
    __syncthreads();
    unsigned add = 0;
    for (int j = 0; j < w; j++) add += ws[j];
    if (tid < nb) g_blocksum[tid] = x + add - v;  // exclusive
}

__global__ void scatter_kernel(int E) {
    int i = blockIdx.x * blockDim.x + threadIdx.x;
    if (i >= E) return;
    int2 sd = g_edges[i];
    unsigned pos = atomicAdd(&g_cursor[sd.y], 1u) + g_blocksum[sd.y >> 10];
    g_sorted[pos] = sd;
}

// ===========================================================================
// Node kernel: PQ[n] = [ x@(W1a-W1b)+b1 | x@W1b ] in fp16,
// x = [feat(64) | xyz(3)]
// ===========================================================================
__global__ __launch_bounds__(256) void node_pq_kernel(
    const float* __restrict__ xyz, const float* __restrict__ feat,
    const float* __restrict__ W1, const float* __restrict__ b1, int N) {
    __shared__ float ws[67][128];
    __shared__ float xs[32][68];

    int tid = threadIdx.x;
    for (int i = tid; i < 67 * 128; i += 256) {
        int k = i >> 7, c = i & 127;
        float w1b = W1[(k + 67) * 64 + (c & 63)];
        ws[k][c] = (c < 64) ? (W1[k * 64 + c] - w1b) : w1b;
    }
    int n0 = blockIdx.x * 32;
    for (int i = tid; i < 32 * 67; i += 256) {
        int n = i / 67, k = i - n * 67;
        int gn = n0 + n;
        float v = 0.f;
        if (gn < N) v = (k < 64) ? feat[(size_t)gn * 64 + k]
                                 : xyz[(size_t)gn * 3 + (k - 64)];
        xs[n][k] = v;
    }
    __syncthreads();

    int cg = tid & 31, ng = tid >> 5;
    int c0 = cg * 4, nr = ng * 4;
    float acc[4][4];
#pragma unroll
    for (int i = 0; i < 4; i++)
#pragma unroll
        for (int j = 0; j < 4; j++)
            acc[i][j] = (c0 < 64) ? b1[c0 + j] : 0.f;

#pragma unroll 67
    for (int k = 0; k < 67; k++) {
        float4 w = *(const float4*)&ws[k][c0];
#pragma unroll
        for (int i = 0; i < 4; i++) {
            float xv = xs[nr + i][k];
            acc[i][0] = fmaf(xv, w.x, acc[i][0]);
            acc[i][1] = fmaf(xv, w.y, acc[i][1]);
            acc[i][2] = fmaf(xv, w.z, acc[i][2]);
            acc[i][3] = fmaf(xv, w.w, acc[i][3]);
        }
    }
#pragma unroll
    for (int i = 0; i < 4; i++) {
        int gn = n0 + nr + i;
        if (gn < N) {
            __half2 h0 = __floats2half2_rn(acc[i][0], acc[i][1]);
            __half2 h1 = __floats2half2_rn(acc[i][2], acc[i][3]);
            uint2 v = make_uint2(*(uint32_t*)&h0, *(uint32_t*)&h1);
            *(uint2*)&g_PQh[(size_t)gn * 128 + c0] = v;
        }
    }
}

// ===========================================================================
// Init output to -inf bits (vectorized).
// Finalize: -inf -> 0 (no incoming edges), else add b2[col] (bias commutes
// with max, so it is applied once here instead of per-edge).
// ===========================================================================
__global__ void init_kernel(uint4* __restrict__ out, int n4) {
    int i = blockIdx.x * blockDim.x + threadIdx.x;
    if (i < n4)
        out[i] = make_uint4(0xff800000u, 0xff800000u, 0xff800000u, 0xff800000u);
}

__global__ void finalize_kernel(uint4* __restrict__ out,
                                const float* __restrict__ b2, int n4) {
    int i = blockIdx.x * blockDim.x + threadIdx.x;
    if (i >= n4) return;
    uint4 v = out[i];
    float4 b = ((const float4*)b2)[i & 15];  // 16 uint4 per 64-col row
    float4 r;
    r.x = (v.x == 0xff800000u) ? 0.f : __uint_as_float(v.x) + b.x;
    r.y = (v.y == 0xff800000u) ? 0.f : __uint_as_float(v.y) + b.y;
    r.z = (v.z == 0xff800000u) ? 0.f : __uint_as_float(v.z) + b.z;
    r.w = (v.w == 0xff800000u) ? 0.f : __uint_as_float(v.w) + b.w;
    *(float4*)&out[i] = r;
}

// ===========================================================================
// Float atomic max via int/uint ordering trick (no return -> RED).
// ===========================================================================
__device__ __forceinline__ void atomic_max_f(float* a, float v) {
    if (v >= 0.f)
        atomicMax((int*)a, __float_as_int(v));
    else
        atomicMin((unsigned int*)a, __float_as_uint(v));
}

// ===========================================================================
// Edge HMMA kernel, v9: fp16 P/Q (gather bytes halved; z = HADD2+HMAX2,
// no cvt chain). dst-sorted + contiguous chunks + SMEM-transpose epilogue
// with cross-tile running max. 128 threads = 4 warps, 4 CTAs/SM.
// Gather: 4 edges per group, 8 lanes per edge row (one LDG.128 per 128B
// fp16 row chunk) -> 16 LDG.128 per lane-tile, 64 L1tex wavefronts/tile.
// ===========================================================================
__global__ __launch_bounds__(128, 4) void edge_mma_kernel(
    const float* __restrict__ W2, float* __restrict__ out, int E) {
    __shared__ char zbuf[4][8192];  // per warp: z 4KB (first half); C 8KB
    __shared__ char wtile[8192];    // W2^T fp16 (64 rows n x 128B k)

    const int tid = threadIdx.x;
    const int lane = tid & 31;
    const int wid = tid >> 5;

    // ---- build swizzled W2^T fp16 in SMEM (once per CTA) ----
    for (int i = tid; i < 64 * 64; i += 128) {
        int n = i >> 6, k = i & 63;
        float w = W2[k * 64 + n];
        uint32_t off = (uint32_t)n * 128 + (((uint32_t)(2 * k)) ^ ((uint32_t)(n & 7) << 4));
        *(__half*)(&wtile[off]) = __float2half_rn(w);
    }
    __syncthreads();

    const uint32_t zh_base = smem_u32(&zbuf[wid][0]);
    const uint32_t cbase = zh_base;  // C[32][64] f32 reuses the buffer
    const uint32_t w_base = smem_u32(&wtile[0]);

    // B-frag ldmatrix lane addressing (covers ks pair per x4)
    const uint32_t brow = lane & 7;
    const uint32_t bswz = brow << 4;
    const uint32_t bpart = (((uint32_t)lane >> 3) & 1) * 16 + (((uint32_t)lane >> 4) & 1) * 32;
    const uint32_t boff0 = brow * 128 + (bpart ^ bswz);        // ks0,ks1
    const uint32_t boff1 = brow * 128 + ((bpart + 64) ^ bswz); // ks2,ks3

    // A-frag ldmatrix lane addressing
    const int am = lane >> 3, rowin = lane & 7;
    const uint32_t lswz = (uint32_t)rowin << 4;
    const uint32_t akb = (uint32_t)((am >> 1) << 4);
    const int arow_in = ((am & 1) << 3) + rowin;

    // C-store lane addressing
    const int crow = lane >> 2;                     // fragment row within 8
    const uint32_t ccb = (uint32_t)(lane & 3) * 8;  // col bytes within n-tile

    // cooperative-gather lane pieces: 4 edges per group, 8 lanes per edge
    const int sub = lane >> 3;                // which edge of the quad
    const int cq = lane & 7;                  // 16B chunk within 128B row
    const uint32_t cbyte = (uint32_t)cq * 16; // byte offset in fp16 row

    const __half2 zero2 = __float2half2_rn(0.f);

    // ---- contiguous chunk assignment ----
    const int T = (E + 31) >> 5;
    const int nwarp = gridDim.x * 4;
    const int gw = blockIdx.x * 4 + wid;
    const int chunk = (T + nwarp - 1) / nwarp;
    int t = gw * chunk;
    const int tend = (t + chunk < T) ? t + chunk : T;
    if (t >= tend) return;

    int e0 = t * 32 + lane;
    int2 sd = g_sorted[(e0 < E) ? e0 : 0];

    // running segmented-max state (carried across tiles)
    int curD = -1;
    float m0 = 0.f, m1 = 0.f;

    for (; t < tend; t++) {
        int e = t * 32 + lane;
        bool valid = (e < E);
        int mydst = valid ? sd.y : -1;

        __syncwarp();  // prior tile's C reads done before gather overwrite

        // ---- cooperative gather (fp16) + relu -> SMEM ----
#pragma unroll 4
        for (int g = 0; g < 8; g++) {
            int esel = 4 * g + sub;
            int d = __shfl_sync(FULLM, sd.y, esel);
            int s = __shfl_sync(FULLM, sd.x, esel);
            uint4 pv = *((const uint4*)(g_PQh + (size_t)d * 128) + cq);
            uint4 qv = *((const uint4*)(g_PQh + (size_t)s * 128 + 64) + cq);
            __half2 z0 = __hmax2(__hadd2(*(__half2*)&pv.x, *(__half2*)&qv.x), zero2);
            __half2 z1 = __hmax2(__hadd2(*(__half2*)&pv.y, *(__half2*)&qv.y), zero2);
            __half2 z2 = __hmax2(__hadd2(*(__half2*)&pv.z, *(__half2*)&qv.z), zero2);
            __half2 z3 = __hmax2(__hadd2(*(__half2*)&pv.w, *(__half2*)&qv.w), zero2);
            uint32_t row = (uint32_t)(4 * g + sub);
            uint32_t off = row * 128 + (cbyte ^ ((row & 7) << 4));
            asm volatile("st.shared.v4.b32 [%0], {%1,%2,%3,%4};"
                         :: "r"(zh_base + off),
                            "r"(*(uint32_t*)&z0), "r"(*(uint32_t*)&z1),
                            "r"(*(uint32_t*)&z2), "r"(*(uint32_t*)&z3));
        }
        __syncwarp();

        // ---- prefetch next tile's edge record (sequential) ----
        if (t + 1 < tend) {
            int en = (t + 1) * 32 + lane;
            sd = g_sorted[(en < E) ? en : 0];
        }

        // ---- load ALL A fragments up-front (frees z-buffer for C) ----
        uint32_t ah[8][4];  // [mt*4+ks]
#pragma unroll
        for (int mt = 0; mt < 2; mt++) {
            uint32_t rowb = (uint32_t)(mt * 16 + arow_in) * 128;
#pragma unroll
            for (int ks = 0; ks < 4; ks++) {
                uint32_t off = rowb + (((uint32_t)ks * 32 + akb) ^ lswz);
                ldmatrix_x4(ah[mt * 4 + ks], zh_base + off);
            }
        }
        // In-warp shared ops are processed in program order: the LDSM reads
        // above complete before the C stores below touch the same bytes.

#pragma unroll
        for (int nt = 0; nt < 8; nt++) {
            uint32_t bw[4][2];
            uint32_t wb = (uint32_t)nt * 1024;
            ldmatrix_x4(&bw[0][0], w_base + wb + boff0);
            ldmatrix_x4(&bw[2][0], w_base + wb + boff1);
            uint32_t cb = (uint32_t)nt * 32 + ccb;
#pragma unroll
            for (int mt = 0; mt < 2; mt++) {
                float c[4] = {0.f, 0.f, 0.f, 0.f};
#pragma unroll
                for (int ks = 0; ks < 4; ks++) mma16816(c, ah[mt * 4 + ks], bw[ks]);

                int r0 = mt * 16 + crow;
                uint32_t sw = (uint32_t)(r0 & 7) << 5;
                uint32_t a0 = cbase + (uint32_t)r0 * 256 + (cb ^ sw);
                asm volatile("st.shared.v2.f32 [%0], {%1,%2};"
                             :: "r"(a0), "f"(c[0]), "f"(c[1]));
                asm volatile("st.shared.v2.f32 [%0], {%1,%2};"
                             :: "r"(a0 + 2048), "f"(c[2]), "f"(c[3]));  // row+8
            }
        }
        __syncwarp();  // all C stores visible before cross-lane reads

        // ---- serial 32-row sweep: running max per col pair, RED at
        //      dst boundaries only ----
#pragma unroll 8
        for (int r = 0; r < 32; r++) {
            int d = __shfl_sync(FULLM, mydst, r);
            uint32_t off = cbase + (uint32_t)r * 256 +
                           (((uint32_t)lane * 8) ^ ((uint32_t)(r & 7) << 5));
            float y0, y1;
            asm volatile("ld.shared.v2.f32 {%0,%1}, [%2];"
                         : "=f"(y0), "=f"(y1) : "r"(off));
            if (d < 0) continue;  // trailing invalid rows
            if (d != curD) {
                if (curD >= 0) {
                    float* o = out + (size_t)curD * 64 + lane * 2;
                    atomic_max_f(o, m0);
                    atomic_max_f(o + 1, m1);
                }
                curD = d;
                m0 = y0;
                m1 = y1;
            } else {
                m0 = fmaxf(m0, y0);
                m1 = fmaxf(m1, y1);
            }
        }
    }

    // ---- final flush ----
    if (curD >= 0) {
        float* o = out + (size_t)curD * 64 + lane * 2;
        atomic_max_f(o, m0);
        atomic_max_f(o + 1, m1);
    }
}

// ===========================================================================
// Inputs: [0]=xyz (N*3 f32), [1]=feat (N*64 f32), [2]=edge_index (2*E int),
//         [3]=W1 (134*64 f32), [4]=b1 (64), [5]=W2 (64*64), [6]=b2 (64)
// ===========================================================================
extern "C" void kernel_launch(void* const* d_in, const int* in_sizes, int n_in,
                              void* d_out, int out_size) {
    const float* xyz  = (const float*)d_in[0];
    const float* feat = (const float*)d_in[1];
    const void*  eidx = d_in[2];
    const float* W1   = (const float*)d_in[3];
    const float* b1   = (const float*)d_in[4];
    const float* W2   = (const float*)d_in[5];
    const float* b2   = (const float*)d_in[6];
    float* out = (float*)d_out;

    int N = in_sizes[0] / 3;
    int E = in_sizes[2] / 2;
    int outn = N * 64;
    int n4 = outn / 4;
    int nb = (N + 1023) / 1024;

    prep_kernel<<<nb, 1024>>>((const unsigned int*)eidx, N);
    convhist_kernel<<<(E + 255) / 256, 256>>>(eidx, E);
    scan1_kernel<<<nb, 1024>>>(N);
    scan2_kernel<<<1, 128>>>(nb);
    scatter_kernel<<<(E + 255) / 256, 256>>>(E);
    node_pq_kernel<<<(N + 31) / 32, 256>>>(xyz, feat, W1, b1, N);
    init_kernel<<<(n4 + 255) / 256, 256>>>((uint4*)out, n4);

    int Twarp = (E + 31) >> 5;
    int grid = 4 * 148;  // persistent, 4 CTAs/SM
    if (grid > (Twarp + 3) / 4) grid = (Twarp + 3) / 4;
    edge_mma_kernel<<<grid, 128>>>(W2, out, E);

    finalize_kernel<<<(n4 + 255) / 256, 256>>>((uint4*)out, b2, n4);
}

// round 14
// speedup vs baseline: 1.8964x; 1.0262x over previous
#include <cuda_runtime.h>
#include <cuda_fp16.h>
#include <math.h>
#include <stdint.h>

#define NMAX 100000
#define EMAX 1700000
#define FULLM 0xffffffffu

// Scratch: per-node fp16 P (cols 0..63, includes b1) and Q (64..127). 25.6 MB.
__device__ __half g_PQh[(size_t)NMAX * 128];
__device__ int2 g_edges[EMAX];    // packed (src, dst), input order
__device__ int2 g_sorted[EMAX];   // grouped by dst
__device__ unsigned g_hist[NMAX];
__device__ unsigned g_cursor[NMAX];
__device__ unsigned g_blocksum[128];
__device__ unsigned g_scan_ctr;
__device__ int g_is64;

__device__ __forceinline__ uint32_t smem_u32(const void* p) {
    uint32_t a;
    asm("{ .reg .u64 t; cvta.to.shared.u64 t, %1; cvt.u32.u64 %0, t; }"
        : "=r"(a) : "l"(p));
    return a;
}

// m16n8k16 row.col f32 += f16*f16
__device__ __forceinline__ void mma16816(float* c, const uint32_t* a,
                                         const uint32_t* b) {
    asm volatile(
        "mma.sync.aligned.m16n8k16.row.col.f32.f16.f16.f32 "
        "{%0,%1,%2,%3}, {%4,%5,%6,%7}, {%8,%9}, {%0,%1,%2,%3};"
        : "+f"(c[0]), "+f"(c[1]), "+f"(c[2]), "+f"(c[3])
        : "r"(a[0]), "r"(a[1]), "r"(a[2]), "r"(a[3]), "r"(b[0]), "r"(b[1]));
}

__device__ __forceinline__ void ldmatrix_x4(uint32_t* r, uint32_t addr) {
    asm volatile(
        "ldmatrix.sync.aligned.m8n8.x4.shared.b16 {%0,%1,%2,%3}, [%4];"
        : "=r"(r[0]), "=r"(r[1]), "=r"(r[2]), "=r"(r[3]) : "r"(addr));
}

// ===========================================================================
// Prep: zero dst-histogram + scan counter + init out to -inf bits; block 0
// also detects int64 vs int32 edge_index (jax x64-disabled emits int32).
// Grid covers max(N, n4) at 1024 threads/block.
// ===========================================================================
__global__ __launch_bounds__(1024) void prep_init_kernel(
    const unsigned int* __restrict__ ei, uint4* __restrict__ out,
    int N, int n4) {
    int i = blockIdx.x * 1024 + threadIdx.x;
    if (i < N) g_hist[i] = 0u;
    if (i < n4)
        out[i] = make_uint4(0xff800000u, 0xff800000u, 0xff800000u, 0xff800000u);
    if (blockIdx.x == 0) {
        if (threadIdx.x == 0) g_scan_ctr = 0u;
        __shared__ int any;
        if (threadIdx.x == 0) any = 0;
        __syncthreads();
        if (ei[2 * threadIdx.x + 1] != 0u) any = 1;  // benign race
        __syncthreads();
        if (threadIdx.x == 0) g_is64 = (any == 0) ? 1 : 0;
    }
}

// Fused: edge_index (either width) -> packed int2, + dst histogram.
__global__ void convhist_kernel(const void* __restrict__ eidx, int E) {
    int i = blockIdx.x * blockDim.x + threadIdx.x;
    if (i >= E) return;
    int s, d;
    if (g_is64) {
        const long long* e64 = (const long long*)eidx;
        s = (int)e64[i];
        d = (int)e64[E + i];
    } else {
        const int* e32 = (const int*)eidx;
        s = e32[i];
        d = e32[E + i];
    }
    g_edges[i] = make_int2(s, d);
    atomicAdd(&g_hist[d], 1u);
}

// ===========================================================================
// Exclusive scan of g_hist -> g_cursor (per-block) + block sums; the LAST
// block to finish (decoupled via g_scan_ctr) exclusively scans g_blocksum
// in place. scatter adds g_blocksum[d>>10].
// ===========================================================================
__global__ __launch_bounds__(1024) void scan1_kernel(int N) {
    __shared__ unsigned wsum[32];
    __shared__ int last_s;
    int tid = threadIdx.x, lane = tid & 31, w = tid >> 5;
    int i = blockIdx.x * 1024 + tid;
    unsigned v = (i < N) ? g_hist[i] : 0u;
    unsigned x = v;
#pragma unroll
    for (int o = 1; o < 32; o <<= 1) {
        unsigned y = __shfl_up_sync(FULLM, x, o);
        if (lane >= o) x += y;
    }
    if (lane == 31) wsum[w] = x;
    __syncthreads();
    if (w == 0) {
        unsigned s = wsum[lane];
#pragma unroll
        for (int o = 1; o < 32; o <<= 1) {
            unsigned y = __shfl_up_sync(FULLM, s, o);
            if (lane >= o) s += y;
        }
        wsum[lane] = s;
    }
    __syncthreads();
    unsigned incl = x + (w > 0 ? wsum[w - 1] : 0u);
    if (i < N) g_cursor[i] = incl - v;  // exclusive within block
    if (tid == 1023) g_blocksum[blockIdx.x] = incl;

    // decoupled final scan of block sums by the last-finishing block
    __threadfence();
    __syncthreads();
    if (tid == 0) {
        unsigned c = atomicAdd(&g_scan_ctr, 1u);
        last_s = (c == gridDim.x - 1) ? 1 : 0;
    }
    __syncthreads();
    if (last_s) {
        int nb = gridDim.x;  // <= 128
        unsigned bv = (tid < nb) ? g_blocksum[tid] : 0u;
        unsigned bx = bv;
#pragma unroll
        for (int o = 1; o < 32; o <<= 1) {
            unsigned y = __shfl_up_sync(FULLM, bx, o);
            if (lane >= o) bx += y;
        }
        if (lane == 31) wsum[w] = bx;
        __syncthreads();
        unsigned add = 0;
        for (int j = 0; j < w && j < 4; j++) add += wsum[j];
        if (tid < nb) g_blocksum[tid] = bx + add - bv;  // exclusive
    }
}

__global__ void scatter_kernel(int E) {
    int i = blockIdx.x * blockDim.x + threadIdx.x;
    if (i >= E) return;
    int2 sd = g_edges[i];
    unsigned pos = atomicAdd(&g_cursor[sd.y], 1u) + g_blocksum[sd.y >> 10];
    g_sorted[pos] = sd;
}

// ===========================================================================
// Node kernel: PQ[n] = [ x@(W1a-W1b)+b1 | x@W1b ] in fp16,
// x = [feat(64) | xyz(3)]
// ===========================================================================
__global__ __launch_bounds__(256) void node_pq_kernel(
    const float* __restrict__ xyz, const float* __restrict__ feat,
    const float* __restrict__ W1, const float* __restrict__ b1, int N) {
    __shared__ float ws[67][128];
    __shared__ float xs[32][68];

    int tid = threadIdx.x;
    for (int i = tid; i < 67 * 128; i += 256) {
        int k = i >> 7, c = i & 127;
        float w1b = W1[(k + 67) * 64 + (c & 63)];
        ws[k][c] = (c < 64) ? (W1[k * 64 + c] - w1b) : w1b;
    }
    int n0 = blockIdx.x * 32;
    for (int i = tid; i < 32 * 67; i += 256) {
        int n = i / 67, k = i - n * 67;
        int gn = n0 + n;
        float v = 0.f;
        if (gn < N) v = (k < 64) ? feat[(size_t)gn * 64 + k]
                                 : xyz[(size_t)gn * 3 + (k - 64)];
        xs[n][k] = v;
    }
    __syncthreads();

    int cg = tid & 31, ng = tid >> 5;
    int c0 = cg * 4, nr = ng * 4;
    float acc[4][4];
#pragma unroll
    for (int i = 0; i < 4; i++)
#pragma unroll
        for (int j = 0; j < 4; j++)
            acc[i][j] = (c0 < 64) ? b1[c0 + j] : 0.f;

#pragma unroll 67
    for (int k = 0; k < 67; k++) {
        float4 w = *(const float4*)&ws[k][c0];
#pragma unroll
        for (int i = 0; i < 4; i++) {
            float xv = xs[nr + i][k];
            acc[i][0] = fmaf(xv, w.x, acc[i][0]);
            acc[i][1] = fmaf(xv, w.y, acc[i][1]);
            acc[i][2] = fmaf(xv, w.z, acc[i][2]);
            acc[i][3] = fmaf(xv, w.w, acc[i][3]);
        }
    }
#pragma unroll
    for (int i = 0; i < 4; i++) {
        int gn = n0 + nr + i;
        if (gn < N) {
            __half2 h0 = __floats2half2_rn(acc[i][0], acc[i][1]);
            __half2 h1 = __floats2half2_rn(acc[i][2], acc[i][3]);
            uint2 v = make_uint2(*(uint32_t*)&h0, *(uint32_t*)&h1);
            *(uint2*)&g_PQh[(size_t)gn * 128 + c0] = v;
        }
    }
}

// ===========================================================================
// Finalize: -inf -> 0 (no incoming edges), else add b2[col] (bias commutes
// with max, so it is applied once here instead of per-edge).
// ===========================================================================
__global__ void finalize_kernel(uint4* __restrict__ out,
                                const float* __restrict__ b2, int n4) {
    int i = blockIdx.x * blockDim.x + threadIdx.x;
    if (i >= n4) return;
    uint4 v = out[i];
    float4 b = ((const float4*)b2)[i & 15];  // 16 uint4 per 64-col row
    float4 r;
    r.x = (v.x == 0xff800000u) ? 0.f : __uint_as_float(v.x) + b.x;
    r.y = (v.y == 0xff800000u) ? 0.f : __uint_as_float(v.y) + b.y;
    r.z = (v.z == 0xff800000u) ? 0.f : __uint_as_float(v.z) + b.z;
    r.w = (v.w == 0xff800000u) ? 0.f : __uint_as_float(v.w) + b.w;
    *(float4*)&out[i] = r;
}

// ===========================================================================
// Float atomic max via int/uint ordering trick (no return -> RED).
// ===========================================================================
__device__ __forceinline__ void atomic_max_f(float* a, float v) {
    if (v >= 0.f)
        atomicMax((int*)a, __float_as_int(v));
    else
        atomicMin((unsigned int*)a, __float_as_uint(v));
}

// ===========================================================================
// Edge HMMA kernel, v10: software-pipelined tiles (double-buffered z).
// While tile t runs ldmatrix+MMA+sweep, tile t+1's gather LDGs are already
// in flight into the other z buffer -> L2 gather latency is hidden inside
// the warp instead of relying on cross-warp overlap alone.
// Dynamic SMEM 56KB/CTA: [0,8K) W2^T fp16; per warp 12KB = z0 4K | z1 4K |
// Cext 4K. C tile rows 0-15 alias the DEAD current-z buffer, rows 16-31 go
// to Cext (clean mt split). 4 CTAs/SM (224KB). Everything else as v9:
// dst-sorted contiguous chunks, fp16 single-term MMA, SMEM-transpose
// epilogue with cross-tile running max, RED only at dst boundaries.
// ===========================================================================
__global__ __launch_bounds__(128, 4) void edge_mma_kernel(
    const float* __restrict__ W2, float* __restrict__ out, int E) {
    extern __shared__ char dsm[];

    const int tid = threadIdx.x;
    const int lane = tid & 31;
    const int wid = tid >> 5;

    // ---- build swizzled W2^T fp16 in SMEM (once per CTA) ----
    for (int i = tid; i < 64 * 64; i += 128) {
        int n = i >> 6, k = i & 63;
        float w = W2[k * 64 + n];
        uint32_t off = (uint32_t)n * 128 + (((uint32_t)(2 * k)) ^ ((uint32_t)(n & 7) << 4));
        *(__half*)(&dsm[off]) = __float2half_rn(w);
    }
    __syncthreads();

    const uint32_t w_base = smem_u32(&dsm[0]);
    const uint32_t wbuf = w_base + 8192 + (uint32_t)wid * 12288;
    const uint32_t zb0 = wbuf, zb1 = wbuf + 4096, cext = wbuf + 8192;

    // B-frag ldmatrix lane addressing (covers ks pair per x4)
    const uint32_t brow = lane & 7;
    const uint32_t bswz = brow << 4;
    const uint32_t bpart = (((uint32_t)lane >> 3) & 1) * 16 + (((uint32_t)lane >> 4) & 1) * 32;
    const uint32_t boff0 = brow * 128 + (bpart ^ bswz);        // ks0,ks1
    const uint32_t boff1 = brow * 128 + ((bpart + 64) ^ bswz); // ks2,ks3

    // A-frag ldmatrix lane addressing
    const int am = lane >> 3, rowin = lane & 7;
    const uint32_t lswz = (uint32_t)rowin << 4;
    const uint32_t akb = (uint32_t)((am >> 1) << 4);
    const int arow_in = ((am & 1) << 3) + rowin;

    // C-store lane addressing
    const int crow = lane >> 2;                     // fragment row within 8
    const uint32_t ccb = (uint32_t)(lane & 3) * 8;  // col bytes within n-tile

    // cooperative-gather lane pieces: 4 edges per group, 8 lanes per edge
    const int sub = lane >> 3;                // which edge of the quad
    const int cq = lane & 7;                  // 16B chunk within 128B row
    const uint32_t cbyte = (uint32_t)cq * 16; // byte offset in fp16 row

    const __half2 zero2 = __float2half2_rn(0.f);

    // ---- contiguous chunk assignment ----
    const int T = (E + 31) >> 5;
    const int nwarp = gridDim.x * 4;
    const int gw = blockIdx.x * 4 + wid;
    const int chunk = (T + nwarp - 1) / nwarp;
    int t = gw * chunk;
    const int tend = (t + chunk < T) ? t + chunk : T;
    if (t >= tend) return;

    // gather macro-equivalent lambda
    auto gather = [&](int2 sdv, uint32_t zdst) {
#pragma unroll 4
        for (int g = 0; g < 8; g++) {
            int esel = 4 * g + sub;
            int d = __shfl_sync(FULLM, sdv.y, esel);
            int s = __shfl_sync(FULLM, sdv.x, esel);
            uint4 pv = *((const uint4*)(g_PQh + (size_t)d * 128) + cq);
            uint4 qv = *((const uint4*)(g_PQh + (size_t)s * 128 + 64) + cq);
            __half2 z0 = __hmax2(__hadd2(*(__half2*)&pv.x, *(__half2*)&qv.x), zero2);
            __half2 z1 = __hmax2(__hadd2(*(__half2*)&pv.y, *(__half2*)&qv.y), zero2);
            __half2 z2 = __hmax2(__hadd2(*(__half2*)&pv.z, *(__half2*)&qv.z), zero2);
            __half2 z3 = __hmax2(__hadd2(*(__half2*)&pv.w, *(__half2*)&qv.w), zero2);
            uint32_t row = (uint32_t)(4 * g + sub);
            uint32_t off = row * 128 + (cbyte ^ ((row & 7) << 4));
            asm volatile("st.shared.v4.b32 [%0], {%1,%2,%3,%4};"
                         :: "r"(zdst + off),
                            "r"(*(uint32_t*)&z0), "r"(*(uint32_t*)&z1),
                            "r"(*(uint32_t*)&z2), "r"(*(uint32_t*)&z3));
        }
    };

    // ---- pipeline prologue ----
    int e0 = t * 32 + lane;
    int2 sd_cur = g_sorted[(e0 < E) ? e0 : 0];
    gather(sd_cur, zb0);
    int2 sd_nx = sd_cur;
    if (t + 1 < tend) {
        int en = (t + 1) * 32 + lane;
        sd_nx = g_sorted[(en < E) ? en : 0];
    }
    int p = 0;

    // running segmented-max state (carried across tiles)
    int curD = -1;
    float m0 = 0.f, m1 = 0.f;

    for (; t < tend; t++) {
        int e = t * 32 + lane;
        bool valid = (e < E);
        int mydst = valid ? sd_cur.y : -1;
        uint32_t zcur = p ? zb1 : zb0;
        uint32_t znxt = p ? zb0 : zb1;

        __syncwarp();  // prev gather STS visible; prev sweep reads done

        // ---- A fragments for tile t from zcur ----
        uint32_t ah[8][4];  // [mt*4+ks]
#pragma unroll
        for (int mt = 0; mt < 2; mt++) {
            uint32_t rowb = (uint32_t)(mt * 16 + arow_in) * 128;
#pragma unroll
            for (int ks = 0; ks < 4; ks++) {
                uint32_t off = rowb + (((uint32_t)ks * 32 + akb) ^ lswz);
                ldmatrix_x4(ah[mt * 4 + ks], zcur + off);
            }
        }

        // ---- issue next tile's gather (overlaps with MMA below) ----
        bool more = (t + 1 < tend);
        if (more) gather(sd_nx, znxt);
        int2 sd_n2 = sd_nx;
        if (t + 2 < tend) {
            int en2 = (t + 2) * 32 + lane;
            sd_n2 = g_sorted[(en2 < E) ? en2 : 0];
        }

        // ---- MMA + C store (rows 0-15 -> dead zcur, rows 16-31 -> cext) ----
#pragma unroll
        for (int nt = 0; nt < 8; nt++) {
            uint32_t bw[4][2];
            uint32_t wb = (uint32_t)nt * 1024;
            ldmatrix_x4(&bw[0][0], w_base + wb + boff0);
            ldmatrix_x4(&bw[2][0], w_base + wb + boff1);
            uint32_t cb = (uint32_t)nt * 32 + ccb;
#pragma unroll
            for (int mt = 0; mt < 2; mt++) {
                float c[4] = {0.f, 0.f, 0.f, 0.f};
#pragma unroll
                for (int ks = 0; ks < 4; ks++) mma16816(c, ah[mt * 4 + ks], bw[ks]);

                uint32_t chalf = mt ? cext : zcur;
                uint32_t sw = (uint32_t)(crow & 7) << 5;
                uint32_t a0 = chalf + (uint32_t)crow * 256 + (cb ^ sw);
                asm volatile("st.shared.v2.f32 [%0], {%1,%2};"
                             :: "r"(a0), "f"(c[0]), "f"(c[1]));
                asm volatile("st.shared.v2.f32 [%0], {%1,%2};"
                             :: "r"(a0 + 2048), "f"(c[2]), "f"(c[3]));  // +8 rows
            }
        }
        __syncwarp();  // C stores visible before cross-lane reads

        // ---- serial 32-row sweep: running max per col pair, RED at
        //      dst boundaries only ----
#pragma unroll 8
        for (int r = 0; r < 32; r++) {
            int d = __shfl_sync(FULLM, mydst, r);
            uint32_t base = (r < 16) ? zcur : cext;
            uint32_t off = base + (uint32_t)(r & 15) * 256 +
                           (((uint32_t)lane * 8) ^ ((uint32_t)(r & 7) << 5));
            float y0, y1;
            asm volatile("ld.shared.v2.f32 {%0,%1}, [%2];"
                         : "=f"(y0), "=f"(y1) : "r"(off));
            if (d < 0) continue;  // trailing invalid rows
            if (d != curD) {
                if (curD >= 0) {
                    float* o = out + (size_t)curD * 64 + lane * 2;
                    atomic_max_f(o, m0);
                    atomic_max_f(o + 1, m1);
                }
                curD = d;
                m0 = y0;
                m1 = y1;
            } else {
                m0 = fmaxf(m0, y0);
                m1 = fmaxf(m1, y1);
            }
        }

        // ---- rotate pipeline ----
        sd_cur = sd_nx;
        sd_nx = sd_n2;
        p ^= 1;
    }

    // ---- final flush ----
    if (curD >= 0) {
        float* o = out + (size_t)curD * 64 + lane * 2;
        atomic_max_f(o, m0);
        atomic_max_f(o + 1, m1);
    }
}

#define EDGE_DSMEM (8192 + 4 * 12288)

// ===========================================================================
// Inputs: [0]=xyz (N*3 f32), [1]=feat (N*64 f32), [2]=edge_index (2*E int),
//         [3]=W1 (134*64 f32), [4]=b1 (64), [5]=W2 (64*64), [6]=b2 (64)
// ===========================================================================
extern "C" void kernel_launch(void* const* d_in, const int* in_sizes, int n_in,
                              void* d_out, int out_size) {
    const float* xyz  = (const float*)d_in[0];
    const float* feat = (const float*)d_in[1];
    const void*  eidx = d_in[2];
    const float* W1   = (const float*)d_in[3];
    const float* b1   = (const float*)d_in[4];
    const float* W2   = (const float*)d_in[5];
    const float* b2   = (const float*)d_in[6];
    float* out = (float*)d_out;

    int N = in_sizes[0] / 3;
    int E = in_sizes[2] / 2;
    int outn = N * 64;
    int n4 = outn / 4;
    int nb = (N + 1023) / 1024;
    int nbig = (n4 > N ? n4 : N);
    int nbp = (nbig + 1023) / 1024;

    cudaFuncSetAttribute(edge_mma_kernel,
                         cudaFuncAttributeMaxDynamicSharedMemorySize,
                         EDGE_DSMEM);

    prep_init_kernel<<<nbp, 1024>>>((const unsigned int*)eidx, (uint4*)out,
                                    N, n4);
    convhist_kernel<<<(E + 255) / 256, 256>>>(eidx, E);
    scan1_kernel<<<nb, 1024>>>(N);
    scatter_kernel<<<(E + 255) / 256, 256>>>(E);
    node_pq_kernel<<<(N + 31) / 32, 256>>>(xyz, feat, W1, b1, N);

    int Twarp = (E + 31) >> 5;
    int grid = 4 * 148;  // persistent, 4 CTAs/SM
    if (grid > (Twarp + 3) / 4) grid = (Twarp + 3) / 4;
    edge_mma_kernel<<<grid, 128, EDGE_DSMEM>>>(W2, out, E);

    finalize_kernel<<<(n4 + 255) / 256, 256>>>((uint4*)out, b2, n4);
}